// round 1
// baseline (speedup 1.0000x reference)
#include <cuda_runtime.h>
#include <cstdint>
#include <math.h>

// Problem constants (fixed shapes for this problem)
#define CN      100000
#define CE      1600000
#define CNFEAT  512
#define CNLABEL 64
#define CNHID   256
#define CDIN    576     // NFEAT + NLABEL
#define CHID2   512     // 2*NHID

// ---------------- scratch (device globals; no allocation allowed) ----------
__device__ float g_h0 [(size_t)CN * CDIN];   // concat(x, one_hot) input
__device__ float g_t  [(size_t)CN * CNHID];  // GEMM output / message source
__device__ float g_acc[(size_t)CN * CNHID];  // aggregation accumulator
__device__ float g_h  [(size_t)CN * CNHID];  // hidden state (layer input)
__device__ float g_m  [(size_t)CN * CHID2];  // MLP hidden
__device__ float g_dinv[CN];                 // deg^{-1/2}

// ---------------- elementwise / setup kernels ------------------------------
__global__ void k_build_h0(const float* __restrict__ x, int n) {
    long long i = (long long)blockIdx.x * blockDim.x + threadIdx.x;
    long long total = (long long)n * CDIN;
    if (i >= total) return;
    int col = (int)(i % CDIN);
    long long row = i / CDIN;
    g_h0[i] = (col < CNFEAT) ? x[row * CNFEAT + col] : 0.0f;
}

__global__ void k_set_labels(const int* __restrict__ idxl, const int* __restrict__ y, int L) {
    int t = blockIdx.x * blockDim.x + threadIdx.x;
    if (t >= L) return;
    int node = idxl[t];
    int lab = y[node];
    if (lab >= 0 && lab < CNLABEL)
        g_h0[(size_t)node * CDIN + CNFEAT + lab] = 1.0f;
}

__global__ void k_deg_init(int n) {
    int i = blockIdx.x * blockDim.x + threadIdx.x;
    if (i < n) g_dinv[i] = 2.0f;   // self-loop weight (improved=True)
}

__global__ void k_deg_edges(const int* __restrict__ adj, int E) {
    int e = blockIdx.x * blockDim.x + threadIdx.x;
    if (e >= E) return;
    atomicAdd(&g_dinv[adj[E + e]], 1.0f);   // adj[1][e] = aggregation target
}

__global__ void k_deg_finish(int n) {
    int i = blockIdx.x * blockDim.x + threadIdx.x;
    if (i < n) {
        float d = g_dinv[i];
        g_dinv[i] = (d > 0.0f) ? rsqrtf(d) : 0.0f;
    }
}

// acc[i,:] = 2 * dinv[i]^2 * t[i,:]   (self-loop message, coalesced, no atomics)
__global__ void k_agg_self(int n) {
    long long i = (long long)blockIdx.x * blockDim.x + threadIdx.x;
    if (i >= (long long)n * CNHID) return;
    int row = (int)(i / CNHID);
    float d = g_dinv[row];
    g_acc[i] = 2.0f * d * d * g_t[i];
}

// One warp per edge: acc[dst,:] += dinv[src]*dinv[dst] * t[src,:]
__global__ void k_agg_edges(const int* __restrict__ adj, int E) {
    int gt = blockIdx.x * blockDim.x + threadIdx.x;
    int warp = gt >> 5;
    int lane = gt & 31;
    if (warp >= E) return;
    int src = adj[warp];
    int dst = adj[E + warp];
    float w = g_dinv[src] * g_dinv[dst];
    const float* ts = g_t + (size_t)src * CNHID;
    float* ad = g_acc + (size_t)dst * CNHID;
#pragma unroll
    for (int k = 0; k < CNHID / 32; k++) {
        int f = k * 32 + lane;
        atomicAdd(&ad[f], w * ts[f]);
    }
}

// h = relu(acc + b)
__global__ void k_relu_bias(const float* __restrict__ b, int n) {
    long long i = (long long)blockIdx.x * blockDim.x + threadIdx.x;
    if (i >= (long long)n * CNHID) return;
    int c = (int)(i % CNHID);
    float v = g_acc[i] + b[c];
    g_h[i] = v > 0.0f ? v : 0.0f;
}

// in-place log_softmax over rows of 64 (one warp per row, 2 elems/lane)
__global__ void k_logsoftmax64(float* __restrict__ out, int n) {
    int gt = blockIdx.x * blockDim.x + threadIdx.x;
    int warp = gt >> 5;
    int lane = gt & 31;
    if (warp >= n) return;
    float* r = out + (size_t)warp * 64;
    float v0 = r[lane], v1 = r[lane + 32];
    float m = fmaxf(v0, v1);
#pragma unroll
    for (int o = 16; o; o >>= 1) m = fmaxf(m, __shfl_xor_sync(0xffffffffu, m, o));
    float s = expf(v0 - m) + expf(v1 - m);
#pragma unroll
    for (int o = 16; o; o >>= 1) s += __shfl_xor_sync(0xffffffffu, s, o);
    float l = m + logf(s);
    r[lane] = v0 - l;
    r[lane + 32] = v1 - l;
}

// ---------------- SGEMM: C[M,N] = A[M,K] @ B[K,N] (+ epilogue) --------------
// BM=128, BN=128, BK=8, 256 threads, 8x8 per-thread register tile.
// EPI: 0 = plain store, 1 = bias + ELU, 2 = bias only
template <int EPI>
__global__ void __launch_bounds__(256)
k_sgemm(const float* __restrict__ A, const float* __restrict__ B,
        float* __restrict__ C, const float* __restrict__ bias,
        int M, int N, int K) {
    __shared__ float As[8][128];
    __shared__ float Bs[8][128];

    int tid = threadIdx.x;
    int row0 = blockIdx.y * 128;
    int col0 = blockIdx.x * 128;

    int tx = tid % 16;        // 16x16 thread grid
    int ty = tid / 16;

    // A loads: 128 rows x 8 cols = 256 float4 (2 per row)
    int aRow = tid >> 1;
    int aCol = (tid & 1) * 4;
    // B loads: 8 rows x 128 cols = 256 float4 (32 per row)
    int bRow = tid >> 5;
    int bCol = (tid & 31) * 4;

    float acc[8][8];
#pragma unroll
    for (int i = 0; i < 8; i++)
#pragma unroll
        for (int j = 0; j < 8; j++) acc[i][j] = 0.0f;

    for (int k0 = 0; k0 < K; k0 += 8) {
        float4 a4 = make_float4(0.f, 0.f, 0.f, 0.f);
        int ar = row0 + aRow;
        if (ar < M) a4 = *(const float4*)&A[(size_t)ar * K + k0 + aCol];
        As[aCol + 0][aRow] = a4.x;
        As[aCol + 1][aRow] = a4.y;
        As[aCol + 2][aRow] = a4.z;
        As[aCol + 3][aRow] = a4.w;

        float4 b4 = make_float4(0.f, 0.f, 0.f, 0.f);
        int bc = col0 + bCol;
        if (bc < N) b4 = *(const float4*)&B[(size_t)(k0 + bRow) * N + bc];
        *(float4*)&Bs[bRow][bCol] = b4;

        __syncthreads();

#pragma unroll
        for (int k = 0; k < 8; k++) {
            float ar_[8], br_[8];
#pragma unroll
            for (int i = 0; i < 8; i++) ar_[i] = As[k][ty * 8 + i];
#pragma unroll
            for (int j = 0; j < 8; j++) br_[j] = Bs[k][tx * 8 + j];
#pragma unroll
            for (int i = 0; i < 8; i++)
#pragma unroll
                for (int j = 0; j < 8; j++) acc[i][j] += ar_[i] * br_[j];
        }
        __syncthreads();
    }

#pragma unroll
    for (int i = 0; i < 8; i++) {
        int r = row0 + ty * 8 + i;
        if (r >= M) continue;
#pragma unroll
        for (int j = 0; j < 8; j++) {
            int c = col0 + tx * 8 + j;
            if (c >= N) continue;
            float v = acc[i][j];
            if (EPI >= 1) v += bias[c];
            if (EPI == 1) v = v > 0.0f ? v : expm1f(v);   // ELU
            C[(size_t)r * N + c] = v;
        }
    }
}

// ---------------- host orchestration ---------------------------------------
static inline int cdiv(long long a, long long b) { return (int)((a + b - 1) / b); }

extern "C" void kernel_launch(void* const* d_in, const int* in_sizes, int n_in,
                              void* d_out, int out_size) {
    const float* x    = (const float*)d_in[0];
    const int*   y    = (const int*)  d_in[1];
    // d_in[2] = predictions (unused by reference)
    const int*   adj  = (const int*)  d_in[3];
    const int*   idxl = (const int*)  d_in[4];
    // d_in[5] = n_sample (unused; mean over 1 sample = identity)
    const float* W0  = (const float*)d_in[6];
    const float* b0  = (const float*)d_in[7];
    const float* W1  = (const float*)d_in[8];
    const float* b1  = (const float*)d_in[9];
    const float* W2  = (const float*)d_in[10];
    const float* b2  = (const float*)d_in[11];
    const float* Wm0 = (const float*)d_in[12];
    const float* bm0 = (const float*)d_in[13];
    const float* Wm1 = (const float*)d_in[14];
    const float* bm1 = (const float*)d_in[15];

    int N = in_sizes[1];          // y has N entries
    int E = in_sizes[3] / 2;
    int L = in_sizes[4];
    float* out = (float*)d_out;

    // device-global scratch pointers (lookup only — no allocation, capture-safe)
    float *p_h0, *p_t, *p_acc, *p_h, *p_m;
    cudaGetSymbolAddress((void**)&p_h0,  g_h0);
    cudaGetSymbolAddress((void**)&p_t,   g_t);
    cudaGetSymbolAddress((void**)&p_acc, g_acc);
    cudaGetSymbolAddress((void**)&p_h,   g_h);
    cudaGetSymbolAddress((void**)&p_m,   g_m);

    const int TB = 256;

    // ---- build input features: h0 = [x | one_hot(labels)] ----
    k_build_h0<<<cdiv((long long)N * CDIN, TB), TB>>>(x, N);
    k_set_labels<<<cdiv(L, TB), TB>>>(idxl, y, L);

    // ---- GCN normalization: deg -> dinv ----
    k_deg_init<<<cdiv(N, TB), TB>>>(N);
    k_deg_edges<<<cdiv(E, TB), TB>>>(adj, E);
    k_deg_finish<<<cdiv(N, TB), TB>>>(N);

    // ---- GCN layer 1: t = h0 @ W0 ; aggregate ; relu(+b0) -> h ----
    {
        dim3 grid(cdiv(CNHID, 128), cdiv(N, 128));
        k_sgemm<0><<<grid, 256>>>(p_h0, W0, p_t, nullptr, N, CNHID, CDIN);
        k_agg_self<<<cdiv((long long)N * CNHID, TB), TB>>>(N);
        k_agg_edges<<<cdiv((long long)E * 32, TB), TB>>>(adj, E);
        k_relu_bias<<<cdiv((long long)N * CNHID, TB), TB>>>(b0, N);
    }
    // ---- GCN layer 2 ----
    {
        dim3 grid(cdiv(CNHID, 128), cdiv(N, 128));
        k_sgemm<0><<<grid, 256>>>(p_h, W1, p_t, nullptr, N, CNHID, CNHID);
        k_agg_self<<<cdiv((long long)N * CNHID, TB), TB>>>(N);
        k_agg_edges<<<cdiv((long long)E * 32, TB), TB>>>(adj, E);
        k_relu_bias<<<cdiv((long long)N * CNHID, TB), TB>>>(b1, N);
    }
    // ---- GCN layer 3 ----
    {
        dim3 grid(cdiv(CNHID, 128), cdiv(N, 128));
        k_sgemm<0><<<grid, 256>>>(p_h, W2, p_t, nullptr, N, CNHID, CNHID);
        k_agg_self<<<cdiv((long long)N * CNHID, TB), TB>>>(N);
        k_agg_edges<<<cdiv((long long)E * 32, TB), TB>>>(adj, E);
        k_relu_bias<<<cdiv((long long)N * CNHID, TB), TB>>>(b2, N);
    }

    // ---- MLP head: m = elu(h @ Wm0 + bm0) ; logits = m @ Wm1 + bm1 ----
    {
        dim3 grid(cdiv(CHID2, 128), cdiv(N, 128));
        k_sgemm<1><<<grid, 256>>>(p_h, Wm0, p_m, bm0, N, CHID2, CNHID);
    }
    {
        dim3 grid(cdiv(CNLABEL, 128), cdiv(N, 128));
        k_sgemm<2><<<grid, 256>>>(p_m, Wm1, out, bm1, N, CNLABEL, CHID2);
    }

    // ---- log_softmax over 64 classes, in-place on d_out ----
    k_logsoftmax64<<<cdiv((long long)N * 32, TB), TB>>>(out, N);
}

// round 2
// speedup vs baseline: 1.1934x; 1.1934x over previous
#include <cuda_runtime.h>
#include <cstdint>
#include <math.h>

// Problem constants (fixed shapes)
#define CN      100000
#define CE      1600000
#define CNFEAT  512
#define CNLABEL 64
#define CNHID   256
#define CDIN    576
#define CHID2   512

// ---------------- scratch (device globals) ----------------------------------
__device__ float g_h0 [(size_t)CN * CDIN];
__device__ float g_t  [(size_t)CN * CNHID];
__device__ float g_acc[(size_t)CN * CNHID];
__device__ float g_h  [(size_t)CN * CNHID];
__device__ float g_m  [(size_t)CN * CHID2];
__device__ float g_dinv[CN];

// ---------------- setup / elementwise kernels -------------------------------
__global__ void k_build_h0(const float* __restrict__ x, int n) {
    long long i = (long long)blockIdx.x * blockDim.x + threadIdx.x;
    long long total = (long long)n * CDIN;
    if (i >= total) return;
    int col = (int)(i % CDIN);
    long long row = i / CDIN;
    g_h0[i] = (col < CNFEAT) ? x[row * CNFEAT + col] : 0.0f;
}

__global__ void k_set_labels(const int* __restrict__ idxl, const int* __restrict__ y, int L) {
    int t = blockIdx.x * blockDim.x + threadIdx.x;
    if (t >= L) return;
    int node = idxl[t];
    int lab = y[node];
    if (lab >= 0 && lab < CNLABEL)
        g_h0[(size_t)node * CDIN + CNFEAT + lab] = 1.0f;
}

__global__ void k_deg_init(int n) {
    int i = blockIdx.x * blockDim.x + threadIdx.x;
    if (i < n) g_dinv[i] = 2.0f;
}

__global__ void k_deg_edges(const int* __restrict__ adj, int E) {
    int e = blockIdx.x * blockDim.x + threadIdx.x;
    if (e >= E) return;
    atomicAdd(&g_dinv[adj[E + e]], 1.0f);
}

__global__ void k_deg_finish(int n) {
    int i = blockIdx.x * blockDim.x + threadIdx.x;
    if (i < n) {
        float d = g_dinv[i];
        g_dinv[i] = (d > 0.0f) ? rsqrtf(d) : 0.0f;
    }
}

// One warp per edge: acc[dst,:] += dinv[src]*dinv[dst] * t[src,:]
__global__ void k_agg_edges(const int* __restrict__ adj, int E) {
    int gt = blockIdx.x * blockDim.x + threadIdx.x;
    int warp = gt >> 5;
    int lane = gt & 31;
    if (warp >= E) return;
    int src = adj[warp];
    int dst = adj[E + warp];
    float w = g_dinv[src] * g_dinv[dst];
    const float* ts = g_t + (size_t)src * CNHID;
    float* ad = g_acc + (size_t)dst * CNHID;
#pragma unroll
    for (int k = 0; k < CNHID / 32; k++) {
        int f = k * 32 + lane;
        atomicAdd(&ad[f], w * ts[f]);
    }
}

__global__ void k_relu_bias(const float* __restrict__ b, int n) {
    long long i = (long long)blockIdx.x * blockDim.x + threadIdx.x;
    if (i >= (long long)n * CNHID) return;
    int c = (int)(i % CNHID);
    float v = g_acc[i] + b[c];
    g_h[i] = v > 0.0f ? v : 0.0f;
}

__global__ void k_logsoftmax64(float* __restrict__ out, int n) {
    int gt = blockIdx.x * blockDim.x + threadIdx.x;
    int warp = gt >> 5;
    int lane = gt & 31;
    if (warp >= n) return;
    float* r = out + (size_t)warp * 64;
    float v0 = r[lane], v1 = r[lane + 32];
    float m = fmaxf(v0, v1);
#pragma unroll
    for (int o = 16; o; o >>= 1) m = fmaxf(m, __shfl_xor_sync(0xffffffffu, m, o));
    float s = expf(v0 - m) + expf(v1 - m);
#pragma unroll
    for (int o = 16; o; o >>= 1) s += __shfl_xor_sync(0xffffffffu, s, o);
    float l = m + logf(s);
    r[lane] = v0 - l;
    r[lane + 32] = v1 - l;
}

// ---------------- TF32 tensor-core GEMM (3xTF32 split for fp32 accuracy) ----
// C[M,N] = A[M,K] @ B[K,N], row-major. BM=128, BN in {64,128}, BK=16.
// EPI: 0 plain | 1 bias+ELU | 2 bias | 3 write C and acc_out = 2*dinv[r]^2 * C

__device__ __forceinline__ void tf32_split(float x, uint32_t& hi, uint32_t& lo) {
    uint32_t h;
    asm("cvt.rna.tf32.f32 %0, %1;" : "=r"(h) : "f"(x));
    float hf = __uint_as_float(h);
    float l = x - hf;
    uint32_t lr;
    asm("cvt.rna.tf32.f32 %0, %1;" : "=r"(lr) : "f"(l));
    hi = h; lo = lr;
}

__device__ __forceinline__ void mma_tf32(float* c, const uint32_t* a, const uint32_t* b) {
    asm volatile(
        "mma.sync.aligned.m16n8k8.row.col.f32.tf32.tf32.f32 "
        "{%0,%1,%2,%3}, {%4,%5,%6,%7}, {%8,%9}, {%0,%1,%2,%3};\n"
        : "+f"(c[0]), "+f"(c[1]), "+f"(c[2]), "+f"(c[3])
        : "r"(a[0]), "r"(a[1]), "r"(a[2]), "r"(a[3]), "r"(b[0]), "r"(b[1]));
}

template <int BN, int EPI>
__global__ void __launch_bounds__(BN * 2)
k_tc_gemm(const float* __restrict__ A, const float* __restrict__ B,
          float* __restrict__ C, const float* __restrict__ bias,
          float* __restrict__ acc_out, const float* __restrict__ dinv,
          int M, int N, int K) {
    constexpr int NT   = BN * 2;      // threads (128 or 256)
    constexpr int NWN  = BN / 32;     // warps along n
    constexpr int ASTR = 136;         // 128 + 8 pad (bank-conflict-free frags)
    constexpr int BSTR = BN + 8;
    constexpr int A_L  = 512 / NT;    // float4 loads per thread for A tile
    constexpr int B_L  = (16 * BN / 4) / NT;

    __shared__ float As[2][16][ASTR];
    __shared__ float Bs[2][16][BSTR];

    const int tid  = threadIdx.x;
    const int wid  = tid >> 5, lane = tid & 31;
    const int grp  = lane >> 2, qid = lane & 3;
    const int warp_m = wid / NWN, warp_n = wid % NWN;
    const int row0 = blockIdx.y * 128;
    const int col0 = blockIdx.x * BN;

    float acc[4][4][4];
#pragma unroll
    for (int i = 0; i < 4; i++)
#pragma unroll
        for (int j = 0; j < 4; j++)
#pragma unroll
            for (int c = 0; c < 4; c++) acc[i][j][c] = 0.0f;

    float4 pa[A_L], pb[B_L];

    // ---- global loads into regs ----
    auto loadG = [&](int k0) {
#pragma unroll
        for (int i = 0; i < A_L; i++) {
            int lin = tid + i * NT;          // 0..511
            int r = lin >> 2, c = (lin & 3) * 4;
            int gr = row0 + r;
            pa[i] = (gr < M) ? *(const float4*)&A[(size_t)gr * K + k0 + c]
                             : make_float4(0.f, 0.f, 0.f, 0.f);
        }
#pragma unroll
        for (int i = 0; i < B_L; i++) {
            int lin = tid + i * NT;          // 0..16*BN/4-1
            int r = lin / (BN / 4), c = (lin % (BN / 4)) * 4;
            pb[i] = *(const float4*)&B[(size_t)(k0 + r) * N + col0 + c];
        }
    };
    // ---- regs -> smem ----
    auto storeS = [&](int buf) {
#pragma unroll
        for (int i = 0; i < A_L; i++) {
            int lin = tid + i * NT;
            int r = lin >> 2, c = (lin & 3) * 4;
            As[buf][c + 0][r] = pa[i].x;
            As[buf][c + 1][r] = pa[i].y;
            As[buf][c + 2][r] = pa[i].z;
            As[buf][c + 3][r] = pa[i].w;
        }
#pragma unroll
        for (int i = 0; i < B_L; i++) {
            int lin = tid + i * NT;
            int r = lin / (BN / 4), c = (lin % (BN / 4)) * 4;
            *(float4*)&Bs[buf][r][c] = pb[i];
        }
    };

    loadG(0);
    storeS(0);
    __syncthreads();

    const int ntiles = K / 16;
    for (int t = 0; t < ntiles; t++) {
        int buf = t & 1;
        if (t + 1 < ntiles) loadG((t + 1) * 16);

#pragma unroll
        for (int ks = 0; ks < 2; ks++) {
            uint32_t bh[4][2], bl[4][2];
#pragma unroll
            for (int nt = 0; nt < 4; nt++) {
                int nn = warp_n * 32 + nt * 8 + grp;
                float b0 = Bs[buf][ks * 8 + qid][nn];
                float b1 = Bs[buf][ks * 8 + qid + 4][nn];
                tf32_split(b0, bh[nt][0], bl[nt][0]);
                tf32_split(b1, bh[nt][1], bl[nt][1]);
            }
#pragma unroll
            for (int mt = 0; mt < 4; mt++) {
                int mm = warp_m * 64 + mt * 16 + grp;
                float a0 = As[buf][ks * 8 + qid][mm];
                float a1 = As[buf][ks * 8 + qid][mm + 8];
                float a2 = As[buf][ks * 8 + qid + 4][mm];
                float a3 = As[buf][ks * 8 + qid + 4][mm + 8];
                uint32_t ah[4], al[4];
                tf32_split(a0, ah[0], al[0]);
                tf32_split(a1, ah[1], al[1]);
                tf32_split(a2, ah[2], al[2]);
                tf32_split(a3, ah[3], al[3]);
#pragma unroll
                for (int nt = 0; nt < 4; nt++) {
                    mma_tf32(acc[mt][nt], ah, bh[nt]);   // hi*hi
                    mma_tf32(acc[mt][nt], ah, bl[nt]);   // hi*lo
                    mma_tf32(acc[mt][nt], al, bh[nt]);   // lo*hi
                }
            }
        }
        if (t + 1 < ntiles) storeS(buf ^ 1);
        __syncthreads();
    }

    // ---- epilogue ----
#pragma unroll
    for (int mt = 0; mt < 4; mt++) {
        int rbase = row0 + warp_m * 64 + mt * 16 + grp;
        float d0 = 0.f, d1 = 0.f;
        if (EPI == 3) {
            if (rbase < M)     { float d = dinv[rbase];     d0 = 2.0f * d * d; }
            if (rbase + 8 < M) { float d = dinv[rbase + 8]; d1 = 2.0f * d * d; }
        }
#pragma unroll
        for (int nt = 0; nt < 4; nt++) {
            int cbase = col0 + warp_n * 32 + nt * 8 + 2 * qid;
#pragma unroll
            for (int half = 0; half < 2; half++) {
                int r = rbase + half * 8;
                if (r >= M) continue;
                float dd = half ? d1 : d0;
#pragma unroll
                for (int e = 0; e < 2; e++) {
                    int c = cbase + e;
                    float v = acc[mt][nt][half * 2 + e];
                    if (EPI == 1 || EPI == 2) v += bias[c];
                    if (EPI == 1) v = v > 0.0f ? v : expm1f(v);
                    C[(size_t)r * N + c] = v;
                    if (EPI == 3) acc_out[(size_t)r * N + c] = dd * v;
                }
            }
        }
    }
}

// ---------------- host orchestration ---------------------------------------
static inline int cdiv(long long a, long long b) { return (int)((a + b - 1) / b); }

extern "C" void kernel_launch(void* const* d_in, const int* in_sizes, int n_in,
                              void* d_out, int out_size) {
    const float* x    = (const float*)d_in[0];
    const int*   y    = (const int*)  d_in[1];
    const int*   adj  = (const int*)  d_in[3];
    const int*   idxl = (const int*)  d_in[4];
    const float* W0  = (const float*)d_in[6];
    const float* b0  = (const float*)d_in[7];
    const float* W1  = (const float*)d_in[8];
    const float* b1  = (const float*)d_in[9];
    const float* W2  = (const float*)d_in[10];
    const float* b2  = (const float*)d_in[11];
    const float* Wm0 = (const float*)d_in[12];
    const float* bm0 = (const float*)d_in[13];
    const float* Wm1 = (const float*)d_in[14];
    const float* bm1 = (const float*)d_in[15];

    int N = in_sizes[1];
    int E = in_sizes[3] / 2;
    int L = in_sizes[4];
    float* out = (float*)d_out;

    float *p_h0, *p_t, *p_acc, *p_h, *p_m, *p_dinv;
    cudaGetSymbolAddress((void**)&p_h0,   g_h0);
    cudaGetSymbolAddress((void**)&p_t,    g_t);
    cudaGetSymbolAddress((void**)&p_acc,  g_acc);
    cudaGetSymbolAddress((void**)&p_h,    g_h);
    cudaGetSymbolAddress((void**)&p_m,    g_m);
    cudaGetSymbolAddress((void**)&p_dinv, g_dinv);

    const int TB = 256;

    // h0 = [x | one_hot(labels)]
    k_build_h0<<<cdiv((long long)N * CDIN, TB), TB>>>(x, N);
    k_set_labels<<<cdiv(L, TB), TB>>>(idxl, y, L);

    // deg -> dinv
    k_deg_init<<<cdiv(N, TB), TB>>>(N);
    k_deg_edges<<<cdiv(E, TB), TB>>>(adj, E);
    k_deg_finish<<<cdiv(N, TB), TB>>>(N);

    dim3 gridH(CNHID / 128, cdiv(N, 128));     // N=256 outputs
    long long ecell = (long long)E * 32;

    // GCN layer 1: t = h0 @ W0 (EPI3 also seeds acc with self-loop term)
    k_tc_gemm<128, 3><<<gridH, 256>>>(p_h0, W0, p_t, nullptr, p_acc, p_dinv, N, CNHID, CDIN);
    k_agg_edges<<<cdiv(ecell, TB), TB>>>(adj, E);
    k_relu_bias<<<cdiv((long long)N * CNHID, TB), TB>>>(b0, N);

    // GCN layer 2
    k_tc_gemm<128, 3><<<gridH, 256>>>(p_h, W1, p_t, nullptr, p_acc, p_dinv, N, CNHID, CNHID);
    k_agg_edges<<<cdiv(ecell, TB), TB>>>(adj, E);
    k_relu_bias<<<cdiv((long long)N * CNHID, TB), TB>>>(b1, N);

    // GCN layer 3
    k_tc_gemm<128, 3><<<gridH, 256>>>(p_h, W2, p_t, nullptr, p_acc, p_dinv, N, CNHID, CNHID);
    k_agg_edges<<<cdiv(ecell, TB), TB>>>(adj, E);
    k_relu_bias<<<cdiv((long long)N * CNHID, TB), TB>>>(b2, N);

    // MLP head
    {
        dim3 grid(CHID2 / 128, cdiv(N, 128));
        k_tc_gemm<128, 1><<<grid, 256>>>(p_h, Wm0, p_m, bm0, nullptr, nullptr, N, CHID2, CNHID);
    }
    {
        dim3 grid(CNLABEL / 64, cdiv(N, 128));
        k_tc_gemm<64, 2><<<grid, 128>>>(p_m, Wm1, out, bm1, nullptr, nullptr, N, CNLABEL, CHID2);
    }

    // log_softmax (64 classes)
    k_logsoftmax64<<<cdiv((long long)N * 32, TB), TB>>>(out, N);
}

// round 3
// speedup vs baseline: 2.1428x; 1.7956x over previous
#include <cuda_runtime.h>
#include <cstdint>
#include <math.h>

// Problem constants (fixed shapes)
#define CN      100000
#define CE      1600000
#define CNFEAT  512
#define CNLABEL 64
#define CNHID   256
#define CHID2   512

// ---------------- scratch (device globals) ----------------------------------
__device__ float g_t  [(size_t)CN * CNHID];   // GEMM output / message source
__device__ float g_h  [(size_t)CN * CNHID];   // hidden state after aggregation
__device__ float g_m  [(size_t)CN * CHID2];   // MLP hidden
__device__ float g_dinv[CN];                  // deg^{-1/2}
__device__ int   g_cnt[CN];                   // in-degree count
__device__ int   g_rowptr[CN + 1];            // CSR row pointers (by dst)
__device__ int   g_cursor[CN];                // fill cursors
__device__ int   g_src[CE];                   // CSR src indices
__device__ float g_w[CE];                     // CSR edge weights dinv*dinv
__device__ int   g_lab[CN];                   // deduped label per node (-1 none)

// ---------------- CSR build --------------------------------------------------
__global__ void k_zero_cnt(int n) {
    int i = blockIdx.x * blockDim.x + threadIdx.x;
    if (i < n) g_cnt[i] = 0;
}

__global__ void k_count(const int* __restrict__ adj, int E) {
    int e = blockIdx.x * blockDim.x + threadIdx.x;
    if (e >= E) return;
    atomicAdd(&g_cnt[adj[E + e]], 1);
}

// single-block exclusive scan of g_cnt -> g_rowptr / g_cursor
__global__ void k_scan(int n, int E) {
    __shared__ int bs[1024];
    int tid = threadIdx.x;
    int chunk = (n + 1023) / 1024;
    int lo = tid * chunk;
    int hi = lo + chunk; if (hi > n) hi = n; if (lo > n) lo = n;
    int s = 0;
    for (int i = lo; i < hi; i++) s += g_cnt[i];
    int mysum = s;
    bs[tid] = s;
    __syncthreads();
    for (int d = 1; d < 1024; d <<= 1) {
        int v = (tid >= d) ? bs[tid - d] : 0;
        __syncthreads();
        bs[tid] += v;
        __syncthreads();
    }
    int off = bs[tid] - mysum;   // exclusive prefix
    for (int i = lo; i < hi; i++) {
        g_rowptr[i] = off;
        g_cursor[i] = off;
        off += g_cnt[i];
    }
    if (tid == 1023) g_rowptr[n] = E;
}

__global__ void k_dinv(int n) {
    int i = blockIdx.x * blockDim.x + threadIdx.x;
    if (i < n) g_dinv[i] = rsqrtf((float)g_cnt[i] + 2.0f);   // deg = cnt + self(2.0)
}

__global__ void k_fill(const int* __restrict__ adj, int E) {
    int e = blockIdx.x * blockDim.x + threadIdx.x;
    if (e >= E) return;
    int src = adj[e];
    int dst = adj[E + e];
    int pos = atomicAdd(&g_cursor[dst], 1);
    g_src[pos] = src;
    g_w[pos] = g_dinv[src] * g_dinv[dst];
}

// ---------------- label one-hot contribution (deduped) -----------------------
__global__ void k_lab_init(int n) {
    int i = blockIdx.x * blockDim.x + threadIdx.x;
    if (i < n) g_lab[i] = -1;
}

__global__ void k_lab_set(const int* __restrict__ idxl, const int* __restrict__ y, int L) {
    int t = blockIdx.x * blockDim.x + threadIdx.x;
    if (t >= L) return;
    int node = idxl[t];
    g_lab[node] = y[node];   // idempotent under duplicates
}

// one warp per node: t[node,:] += W0[512+lab, :]
__global__ void k_lab_add(const float* __restrict__ W0, int n) {
    int gt = blockIdx.x * blockDim.x + threadIdx.x;
    int warp = gt >> 5, lane = gt & 31;
    if (warp >= n) return;
    int lab = g_lab[warp];
    if (lab < 0) return;
    const float* wrow = W0 + (size_t)(CNFEAT + lab) * CNHID;
    float* trow = g_t + (size_t)warp * CNHID;
#pragma unroll
    for (int k = 0; k < CNHID / 32; k++)
        trow[k * 32 + lane] += wrow[k * 32 + lane];
}

// ---------------- fused CSR aggregation: h = relu(bias + self + edges) -------
__global__ void __launch_bounds__(256)
k_agg_csr(const float* __restrict__ t, float* __restrict__ h,
          const float* __restrict__ bias, int n) {
    int warp = (blockIdx.x * blockDim.x + threadIdx.x) >> 5;
    int lane = threadIdx.x & 31;
    if (warp >= n) return;
    int beg = g_rowptr[warp];
    int end = g_rowptr[warp + 1];
    const float* ti = t + (size_t)warp * CNHID;
    float d = g_dinv[warp];
    float sw = 2.0f * d * d;
    float acc[8];
#pragma unroll
    for (int k = 0; k < 8; k++)
        acc[k] = bias[k * 32 + lane] + sw * ti[k * 32 + lane];

    int e = beg;
    // unroll-by-2 over edges for more loads in flight
    for (; e + 1 < end; e += 2) {
        int s0 = g_src[e], s1 = g_src[e + 1];
        float w0 = g_w[e], w1 = g_w[e + 1];
        const float* t0 = t + (size_t)s0 * CNHID;
        const float* t1 = t + (size_t)s1 * CNHID;
        float v0[8], v1[8];
#pragma unroll
        for (int k = 0; k < 8; k++) { v0[k] = t0[k * 32 + lane]; v1[k] = t1[k * 32 + lane]; }
#pragma unroll
        for (int k = 0; k < 8; k++) acc[k] = fmaf(w0, v0[k], acc[k]);
#pragma unroll
        for (int k = 0; k < 8; k++) acc[k] = fmaf(w1, v1[k], acc[k]);
    }
    if (e < end) {
        int s0 = g_src[e];
        float w0 = g_w[e];
        const float* t0 = t + (size_t)s0 * CNHID;
#pragma unroll
        for (int k = 0; k < 8; k++) acc[k] = fmaf(w0, t0[k * 32 + lane], acc[k]);
    }

    float* hrow = h + (size_t)warp * CNHID;
#pragma unroll
    for (int k = 0; k < 8; k++)
        hrow[k * 32 + lane] = fmaxf(acc[k], 0.0f);
}

// ---------------- log_softmax over 64 classes --------------------------------
__global__ void k_logsoftmax64(float* __restrict__ out, int n) {
    int gt = blockIdx.x * blockDim.x + threadIdx.x;
    int warp = gt >> 5, lane = gt & 31;
    if (warp >= n) return;
    float* r = out + (size_t)warp * 64;
    float v0 = r[lane], v1 = r[lane + 32];
    float m = fmaxf(v0, v1);
#pragma unroll
    for (int o = 16; o; o >>= 1) m = fmaxf(m, __shfl_xor_sync(0xffffffffu, m, o));
    float s = expf(v0 - m) + expf(v1 - m);
#pragma unroll
    for (int o = 16; o; o >>= 1) s += __shfl_xor_sync(0xffffffffu, s, o);
    float l = m + logf(s);
    r[lane] = v0 - l;
    r[lane + 32] = v1 - l;
}

// ---------------- TF32 tensor-core GEMM (3xTF32 split) -----------------------
// C[M,N] = A[M,K] @ B[K,N], row-major. BM=128, BN in {64,128}, BK=16.
// EPI: 0 plain | 1 bias+ELU | 2 bias

__device__ __forceinline__ void tf32_split(float x, uint32_t& hi, uint32_t& lo) {
    uint32_t h;
    asm("cvt.rna.tf32.f32 %0, %1;" : "=r"(h) : "f"(x));
    float hf = __uint_as_float(h);
    float l = x - hf;
    uint32_t lr;
    asm("cvt.rna.tf32.f32 %0, %1;" : "=r"(lr) : "f"(l));
    hi = h; lo = lr;
}

__device__ __forceinline__ void mma_tf32(float* c, const uint32_t* a, const uint32_t* b) {
    asm volatile(
        "mma.sync.aligned.m16n8k8.row.col.f32.tf32.tf32.f32 "
        "{%0,%1,%2,%3}, {%4,%5,%6,%7}, {%8,%9}, {%0,%1,%2,%3};\n"
        : "+f"(c[0]), "+f"(c[1]), "+f"(c[2]), "+f"(c[3])
        : "r"(a[0]), "r"(a[1]), "r"(a[2]), "r"(a[3]), "r"(b[0]), "r"(b[1]));
}

template <int BN, int EPI>
__global__ void __launch_bounds__(BN * 2)
k_tc_gemm(const float* __restrict__ A, const float* __restrict__ B,
          float* __restrict__ C, const float* __restrict__ bias,
          int M, int N, int K) {
    constexpr int NT   = BN * 2;
    constexpr int NWN  = BN / 32;
    constexpr int ASTR = 136;
    constexpr int BSTR = BN + 8;
    constexpr int A_L  = 512 / NT;
    constexpr int B_L  = (16 * BN / 4) / NT;

    __shared__ float As[2][16][ASTR];
    __shared__ float Bs[2][16][BSTR];

    const int tid  = threadIdx.x;
    const int wid  = tid >> 5, lane = tid & 31;
    const int grp  = lane >> 2, qid = lane & 3;
    const int warp_m = wid / NWN, warp_n = wid % NWN;
    const int row0 = blockIdx.y * 128;
    const int col0 = blockIdx.x * BN;

    float acc[4][4][4];
#pragma unroll
    for (int i = 0; i < 4; i++)
#pragma unroll
        for (int j = 0; j < 4; j++)
#pragma unroll
            for (int c = 0; c < 4; c++) acc[i][j][c] = 0.0f;

    float4 pa[A_L], pb[B_L];

    auto loadG = [&](int k0) {
#pragma unroll
        for (int i = 0; i < A_L; i++) {
            int lin = tid + i * NT;
            int r = lin >> 2, c = (lin & 3) * 4;
            int gr = row0 + r;
            pa[i] = (gr < M) ? *(const float4*)&A[(size_t)gr * K + k0 + c]
                             : make_float4(0.f, 0.f, 0.f, 0.f);
        }
#pragma unroll
        for (int i = 0; i < B_L; i++) {
            int lin = tid + i * NT;
            int r = lin / (BN / 4), c = (lin % (BN / 4)) * 4;
            pb[i] = *(const float4*)&B[(size_t)(k0 + r) * N + col0 + c];
        }
    };
    auto storeS = [&](int buf) {
#pragma unroll
        for (int i = 0; i < A_L; i++) {
            int lin = tid + i * NT;
            int r = lin >> 2, c = (lin & 3) * 4;
            As[buf][c + 0][r] = pa[i].x;
            As[buf][c + 1][r] = pa[i].y;
            As[buf][c + 2][r] = pa[i].z;
            As[buf][c + 3][r] = pa[i].w;
        }
#pragma unroll
        for (int i = 0; i < B_L; i++) {
            int lin = tid + i * NT;
            int r = lin / (BN / 4), c = (lin % (BN / 4)) * 4;
            *(float4*)&Bs[buf][r][c] = pb[i];
        }
    };

    loadG(0);
    storeS(0);
    __syncthreads();

    const int ntiles = K / 16;
    for (int t = 0; t < ntiles; t++) {
        int buf = t & 1;
        if (t + 1 < ntiles) loadG((t + 1) * 16);

#pragma unroll
        for (int ks = 0; ks < 2; ks++) {
            uint32_t bh[4][2], bl[4][2];
#pragma unroll
            for (int nt = 0; nt < 4; nt++) {
                int nn = warp_n * 32 + nt * 8 + grp;
                float b0 = Bs[buf][ks * 8 + qid][nn];
                float b1 = Bs[buf][ks * 8 + qid + 4][nn];
                tf32_split(b0, bh[nt][0], bl[nt][0]);
                tf32_split(b1, bh[nt][1], bl[nt][1]);
            }
#pragma unroll
            for (int mt = 0; mt < 4; mt++) {
                int mm = warp_m * 64 + mt * 16 + grp;
                float a0 = As[buf][ks * 8 + qid][mm];
                float a1 = As[buf][ks * 8 + qid][mm + 8];
                float a2 = As[buf][ks * 8 + qid + 4][mm];
                float a3 = As[buf][ks * 8 + qid + 4][mm + 8];
                uint32_t ah[4], al[4];
                tf32_split(a0, ah[0], al[0]);
                tf32_split(a1, ah[1], al[1]);
                tf32_split(a2, ah[2], al[2]);
                tf32_split(a3, ah[3], al[3]);
#pragma unroll
                for (int nt = 0; nt < 4; nt++) {
                    mma_tf32(acc[mt][nt], ah, bh[nt]);
                    mma_tf32(acc[mt][nt], ah, bl[nt]);
                    mma_tf32(acc[mt][nt], al, bh[nt]);
                }
            }
        }
        if (t + 1 < ntiles) storeS(buf ^ 1);
        __syncthreads();
    }

#pragma unroll
    for (int mt = 0; mt < 4; mt++) {
        int rbase = row0 + warp_m * 64 + mt * 16 + grp;
#pragma unroll
        for (int nt = 0; nt < 4; nt++) {
            int cbase = col0 + warp_n * 32 + nt * 8 + 2 * qid;
#pragma unroll
            for (int half = 0; half < 2; half++) {
                int r = rbase + half * 8;
                if (r >= M) continue;
#pragma unroll
                for (int e = 0; e < 2; e++) {
                    int c = cbase + e;
                    float v = acc[mt][nt][half * 2 + e];
                    if (EPI == 1 || EPI == 2) v += bias[c];
                    if (EPI == 1) v = v > 0.0f ? v : expm1f(v);
                    C[(size_t)r * N + c] = v;
                }
            }
        }
    }
}

// ---------------- host orchestration ---------------------------------------
static inline int cdiv(long long a, long long b) { return (int)((a + b - 1) / b); }

extern "C" void kernel_launch(void* const* d_in, const int* in_sizes, int n_in,
                              void* d_out, int out_size) {
    const float* x    = (const float*)d_in[0];
    const int*   y    = (const int*)  d_in[1];
    const int*   adj  = (const int*)  d_in[3];
    const int*   idxl = (const int*)  d_in[4];
    const float* W0  = (const float*)d_in[6];
    const float* b0  = (const float*)d_in[7];
    const float* W1  = (const float*)d_in[8];
    const float* b1  = (const float*)d_in[9];
    const float* W2  = (const float*)d_in[10];
    const float* b2  = (const float*)d_in[11];
    const float* Wm0 = (const float*)d_in[12];
    const float* bm0 = (const float*)d_in[13];
    const float* Wm1 = (const float*)d_in[14];
    const float* bm1 = (const float*)d_in[15];

    int N = in_sizes[1];
    int E = in_sizes[3] / 2;
    int L = in_sizes[4];
    float* out = (float*)d_out;

    float *p_t, *p_h, *p_m;
    cudaGetSymbolAddress((void**)&p_t, g_t);
    cudaGetSymbolAddress((void**)&p_h, g_h);
    cudaGetSymbolAddress((void**)&p_m, g_m);

    const int TB = 256;

    // ---- CSR build (also yields degrees -> dinv) ----
    k_zero_cnt<<<cdiv(N, TB), TB>>>(N);
    k_count<<<cdiv(E, TB), TB>>>(adj, E);
    k_scan<<<1, 1024>>>(N, E);
    k_dinv<<<cdiv(N, TB), TB>>>(N);
    k_fill<<<cdiv(E, TB), TB>>>(adj, E);

    // ---- label flags (deduped) ----
    k_lab_init<<<cdiv(N, TB), TB>>>(N);
    k_lab_set<<<cdiv(L, TB), TB>>>(idxl, y, L);

    dim3 gridH(CNHID / 128, cdiv(N, 128));
    long long nwcell = (long long)N * 32;

    // ---- GCN layer 1: t = x @ W0[:512] + one_hot part; aggregate -> h ----
    k_tc_gemm<128, 0><<<gridH, 256>>>(x, W0, p_t, nullptr, N, CNHID, CNFEAT);
    k_lab_add<<<cdiv(nwcell, TB), TB>>>(W0, N);
    k_agg_csr<<<cdiv(nwcell, TB), TB>>>(p_t, p_h, b0, N);

    // ---- GCN layer 2 ----
    k_tc_gemm<128, 0><<<gridH, 256>>>(p_h, W1, p_t, nullptr, N, CNHID, CNHID);
    k_agg_csr<<<cdiv(nwcell, TB), TB>>>(p_t, p_h, b1, N);

    // ---- GCN layer 3 ----
    k_tc_gemm<128, 0><<<gridH, 256>>>(p_h, W2, p_t, nullptr, N, CNHID, CNHID);
    k_agg_csr<<<cdiv(nwcell, TB), TB>>>(p_t, p_h, b2, N);

    // ---- MLP head ----
    {
        dim3 grid(CHID2 / 128, cdiv(N, 128));
        k_tc_gemm<128, 1><<<grid, 256>>>(p_h, Wm0, p_m, bm0, N, CHID2, CNHID);
    }
    {
        dim3 grid(CNLABEL / 64, cdiv(N, 128));
        k_tc_gemm<64, 2><<<grid, 128>>>(p_m, Wm1, out, bm1, N, CNLABEL, CHID2);
    }

    // ---- log_softmax ----
    k_logsoftmax64<<<cdiv(nwcell, TB), TB>>>(out, N);
}

// round 4
// speedup vs baseline: 2.8960x; 1.3515x over previous
#include <cuda_runtime.h>
#include <cuda_fp16.h>
#include <cstdint>
#include <math.h>

// Problem constants (fixed shapes)
#define CN      100000
#define CE      1600000
#define CNFEAT  512
#define CNLABEL 64
#define CNHID   256
#define CHID2   512

// ---------------- scratch (device globals) ----------------------------------
__device__ float g_t  [(size_t)CN * CNHID];
__device__ float g_h  [(size_t)CN * CNHID];
__device__ float g_m  [(size_t)CN * CHID2];
__device__ float g_dinv[CN];
__device__ int   g_cnt[CN];
__device__ int   g_rowptr[CN + 1];
__device__ int   g_cursor[CN];
__device__ int   g_src[CE];
__device__ float g_w[CE];
__device__ int   g_lab[CN];

// ---------------- CSR build --------------------------------------------------
__global__ void k_zero_cnt(int n) {
    int i = blockIdx.x * blockDim.x + threadIdx.x;
    if (i < n) g_cnt[i] = 0;
}

__global__ void k_count(const int* __restrict__ adj, int E) {
    int e = blockIdx.x * blockDim.x + threadIdx.x;
    if (e >= E) return;
    atomicAdd(&g_cnt[adj[E + e]], 1);
}

__global__ void k_scan(int n, int E) {
    __shared__ int bs[1024];
    int tid = threadIdx.x;
    int chunk = (n + 1023) / 1024;
    int lo = tid * chunk;
    int hi = lo + chunk; if (hi > n) hi = n; if (lo > n) lo = n;
    int s = 0;
    for (int i = lo; i < hi; i++) s += g_cnt[i];
    int mysum = s;
    bs[tid] = s;
    __syncthreads();
    for (int d = 1; d < 1024; d <<= 1) {
        int v = (tid >= d) ? bs[tid - d] : 0;
        __syncthreads();
        bs[tid] += v;
        __syncthreads();
    }
    int off = bs[tid] - mysum;
    for (int i = lo; i < hi; i++) {
        g_rowptr[i] = off;
        g_cursor[i] = off;
        off += g_cnt[i];
    }
    if (tid == 1023) g_rowptr[n] = E;
}

__global__ void k_dinv(int n) {
    int i = blockIdx.x * blockDim.x + threadIdx.x;
    if (i < n) g_dinv[i] = rsqrtf((float)g_cnt[i] + 2.0f);
}

__global__ void k_fill(const int* __restrict__ adj, int E) {
    int e = blockIdx.x * blockDim.x + threadIdx.x;
    if (e >= E) return;
    int src = adj[e];
    int dst = adj[E + e];
    int pos = atomicAdd(&g_cursor[dst], 1);
    g_src[pos] = src;
    g_w[pos] = g_dinv[src] * g_dinv[dst];
}

// ---------------- labels ------------------------------------------------------
__global__ void k_lab_init(int n) {
    int i = blockIdx.x * blockDim.x + threadIdx.x;
    if (i < n) g_lab[i] = -1;
}

__global__ void k_lab_set(const int* __restrict__ idxl, const int* __restrict__ y, int L) {
    int t = blockIdx.x * blockDim.x + threadIdx.x;
    if (t >= L) return;
    int node = idxl[t];
    g_lab[node] = y[node];
}

__global__ void k_lab_add(const float* __restrict__ W0, int n) {
    int gt = blockIdx.x * blockDim.x + threadIdx.x;
    int warp = gt >> 5, lane = gt & 31;
    if (warp >= n) return;
    int lab = g_lab[warp];
    if (lab < 0) return;
    const float* wrow = W0 + (size_t)(CNFEAT + lab) * CNHID;
    float* trow = g_t + (size_t)warp * CNHID;
#pragma unroll
    for (int k = 0; k < CNHID / 32; k++)
        trow[k * 32 + lane] += wrow[k * 32 + lane];
}

// ---------------- fused CSR aggregation (float4) ------------------------------
__global__ void __launch_bounds__(256)
k_agg_csr(const float* __restrict__ t, float* __restrict__ h,
          const float* __restrict__ bias, int n) {
    int warp = (blockIdx.x * blockDim.x + threadIdx.x) >> 5;
    int lane = threadIdx.x & 31;
    if (warp >= n) return;
    int beg = g_rowptr[warp];
    int end = g_rowptr[warp + 1];
    const float4* ti = (const float4*)(t + (size_t)warp * CNHID);
    const float4* bi = (const float4*)bias;
    float d = g_dinv[warp];
    float sw = 2.0f * d * d;

    float4 a0 = bi[lane], a1 = bi[32 + lane];
    float4 s0 = ti[lane], s1 = ti[32 + lane];
    a0.x += sw * s0.x; a0.y += sw * s0.y; a0.z += sw * s0.z; a0.w += sw * s0.w;
    a1.x += sw * s1.x; a1.y += sw * s1.y; a1.z += sw * s1.z; a1.w += sw * s1.w;

    int e = beg;
    for (; e + 1 < end; e += 2) {
        int sA = g_src[e], sB = g_src[e + 1];
        float wA = g_w[e], wB = g_w[e + 1];
        const float4* tA = (const float4*)(t + (size_t)sA * CNHID);
        const float4* tB = (const float4*)(t + (size_t)sB * CNHID);
        float4 vA0 = tA[lane], vA1 = tA[32 + lane];
        float4 vB0 = tB[lane], vB1 = tB[32 + lane];
        a0.x = fmaf(wA, vA0.x, a0.x); a0.y = fmaf(wA, vA0.y, a0.y);
        a0.z = fmaf(wA, vA0.z, a0.z); a0.w = fmaf(wA, vA0.w, a0.w);
        a1.x = fmaf(wA, vA1.x, a1.x); a1.y = fmaf(wA, vA1.y, a1.y);
        a1.z = fmaf(wA, vA1.z, a1.z); a1.w = fmaf(wA, vA1.w, a1.w);
        a0.x = fmaf(wB, vB0.x, a0.x); a0.y = fmaf(wB, vB0.y, a0.y);
        a0.z = fmaf(wB, vB0.z, a0.z); a0.w = fmaf(wB, vB0.w, a0.w);
        a1.x = fmaf(wB, vB1.x, a1.x); a1.y = fmaf(wB, vB1.y, a1.y);
        a1.z = fmaf(wB, vB1.z, a1.z); a1.w = fmaf(wB, vB1.w, a1.w);
    }
    if (e < end) {
        int sA = g_src[e];
        float wA = g_w[e];
        const float4* tA = (const float4*)(t + (size_t)sA * CNHID);
        float4 vA0 = tA[lane], vA1 = tA[32 + lane];
        a0.x = fmaf(wA, vA0.x, a0.x); a0.y = fmaf(wA, vA0.y, a0.y);
        a0.z = fmaf(wA, vA0.z, a0.z); a0.w = fmaf(wA, vA0.w, a0.w);
        a1.x = fmaf(wA, vA1.x, a1.x); a1.y = fmaf(wA, vA1.y, a1.y);
        a1.z = fmaf(wA, vA1.z, a1.z); a1.w = fmaf(wA, vA1.w, a1.w);
    }

    float4* hr = (float4*)(h + (size_t)warp * CNHID);
    a0.x = fmaxf(a0.x, 0.f); a0.y = fmaxf(a0.y, 0.f);
    a0.z = fmaxf(a0.z, 0.f); a0.w = fmaxf(a0.w, 0.f);
    a1.x = fmaxf(a1.x, 0.f); a1.y = fmaxf(a1.y, 0.f);
    a1.z = fmaxf(a1.z, 0.f); a1.w = fmaxf(a1.w, 0.f);
    hr[lane] = a0;
    hr[32 + lane] = a1;
}

// ---------------- log_softmax --------------------------------------------------
__global__ void k_logsoftmax64(float* __restrict__ out, int n) {
    int gt = blockIdx.x * blockDim.x + threadIdx.x;
    int warp = gt >> 5, lane = gt & 31;
    if (warp >= n) return;
    float* r = out + (size_t)warp * 64;
    float v0 = r[lane], v1 = r[lane + 32];
    float m = fmaxf(v0, v1);
#pragma unroll
    for (int o = 16; o; o >>= 1) m = fmaxf(m, __shfl_xor_sync(0xffffffffu, m, o));
    float s = expf(v0 - m) + expf(v1 - m);
#pragma unroll
    for (int o = 16; o; o >>= 1) s += __shfl_xor_sync(0xffffffffu, s, o);
    float l = m + logf(s);
    r[lane] = v0 - l;
    r[lane + 32] = v1 - l;
}

// ---------------- split-FP16 tensor-core GEMM ---------------------------------
// C[M,N] = A[M,K] @ B[K,N], row-major. BM=128, BN in {64,128}, BK=16.
// x = hi + lo (both fp16); C = hi*hi + hi*lo + lo*hi (fp32 accumulate).
// EPI: 0 plain | 1 bias+ELU | 2 bias

__device__ __forceinline__ void split2(float x0, float x1, uint32_t& hi, uint32_t& lo) {
    __half2 h = __floats2half2_rn(x0, x1);
    float2 hf = __half22float2(h);
    __half2 l = __floats2half2_rn(x0 - hf.x, x1 - hf.y);
    hi = *reinterpret_cast<uint32_t*>(&h);
    lo = *reinterpret_cast<uint32_t*>(&l);
}

__device__ __forceinline__ void mma_f16(float* c, const uint32_t* a, const uint32_t* b) {
    asm volatile(
        "mma.sync.aligned.m16n8k16.row.col.f32.f16.f16.f32 "
        "{%0,%1,%2,%3}, {%4,%5,%6,%7}, {%8,%9}, {%0,%1,%2,%3};\n"
        : "+f"(c[0]), "+f"(c[1]), "+f"(c[2]), "+f"(c[3])
        : "r"(a[0]), "r"(a[1]), "r"(a[2]), "r"(a[3]), "r"(b[0]), "r"(b[1]));
}

template <int BN, int EPI>
__global__ void __launch_bounds__(BN * 2)
k_tc_gemm(const float* __restrict__ A, const float* __restrict__ B,
          float* __restrict__ C, const float* __restrict__ bias,
          int M, int N, int K) {
    constexpr int NT   = BN * 2;      // threads
    constexpr int NWN  = BN / 32;     // warps along n
    constexpr int ASTR = 132;         // 128 + 4 pad (conflict-free for k-stride 2qid pattern)
    constexpr int BSTR = BN + 4;
    constexpr int A_L  = 512 / NT;
    constexpr int B_L  = (16 * BN / 4) / NT;

    __shared__ float As[2][16][ASTR];
    __shared__ float Bs[2][16][BSTR];

    const int tid  = threadIdx.x;
    const int wid  = tid >> 5, lane = tid & 31;
    const int grp  = lane >> 2, qid = lane & 3;
    const int warp_m = wid / NWN, warp_n = wid % NWN;
    const int row0 = blockIdx.y * 128;
    const int col0 = blockIdx.x * BN;

    float acc[4][4][4];
#pragma unroll
    for (int i = 0; i < 4; i++)
#pragma unroll
        for (int j = 0; j < 4; j++)
#pragma unroll
            for (int c = 0; c < 4; c++) acc[i][j][c] = 0.0f;

    float4 pa[A_L], pb[B_L];

    auto loadG = [&](int k0) {
#pragma unroll
        for (int i = 0; i < A_L; i++) {
            int lin = tid + i * NT;
            int r = lin >> 2, c = (lin & 3) * 4;
            int gr = row0 + r;
            pa[i] = (gr < M) ? *(const float4*)&A[(size_t)gr * K + k0 + c]
                             : make_float4(0.f, 0.f, 0.f, 0.f);
        }
#pragma unroll
        for (int i = 0; i < B_L; i++) {
            int lin = tid + i * NT;
            int r = lin / (BN / 4), c = (lin % (BN / 4)) * 4;
            pb[i] = *(const float4*)&B[(size_t)(k0 + r) * N + col0 + c];
        }
    };
    auto storeS = [&](int buf) {
#pragma unroll
        for (int i = 0; i < A_L; i++) {
            int lin = tid + i * NT;
            int r = lin >> 2, c = (lin & 3) * 4;
            As[buf][c + 0][r] = pa[i].x;
            As[buf][c + 1][r] = pa[i].y;
            As[buf][c + 2][r] = pa[i].z;
            As[buf][c + 3][r] = pa[i].w;
        }
#pragma unroll
        for (int i = 0; i < B_L; i++) {
            int lin = tid + i * NT;
            int r = lin / (BN / 4), c = (lin % (BN / 4)) * 4;
            *(float4*)&Bs[buf][r][c] = pb[i];
        }
    };

    loadG(0);
    storeS(0);
    __syncthreads();

    const int k0a = 2 * qid;            // k indices within BK=16 slab
    const int k1a = 2 * qid + 1;
    const int k8a = 2 * qid + 8;
    const int k9a = 2 * qid + 9;

    const int ntiles = K / 16;
    for (int t = 0; t < ntiles; t++) {
        int buf = t & 1;
        if (t + 1 < ntiles) loadG((t + 1) * 16);

        // B fragments
        uint32_t bh[4][2], bl[4][2];
#pragma unroll
        for (int nt = 0; nt < 4; nt++) {
            int nn = warp_n * 32 + nt * 8 + grp;
            float b0 = Bs[buf][k0a][nn];
            float b1 = Bs[buf][k1a][nn];
            float b2 = Bs[buf][k8a][nn];
            float b3 = Bs[buf][k9a][nn];
            split2(b0, b1, bh[nt][0], bl[nt][0]);
            split2(b2, b3, bh[nt][1], bl[nt][1]);
        }
        // A fragments + mma
#pragma unroll
        for (int mt = 0; mt < 4; mt++) {
            int mm = warp_m * 64 + mt * 16 + grp;
            float a00 = As[buf][k0a][mm],     a01 = As[buf][k1a][mm];
            float a10 = As[buf][k0a][mm + 8], a11 = As[buf][k1a][mm + 8];
            float a02 = As[buf][k8a][mm],     a03 = As[buf][k9a][mm];
            float a12 = As[buf][k8a][mm + 8], a13 = As[buf][k9a][mm + 8];
            uint32_t ah[4], al[4];
            split2(a00, a01, ah[0], al[0]);
            split2(a10, a11, ah[1], al[1]);
            split2(a02, a03, ah[2], al[2]);
            split2(a12, a13, ah[3], al[3]);
#pragma unroll
            for (int nt = 0; nt < 4; nt++) {
                mma_f16(acc[mt][nt], ah, bh[nt]);   // hi*hi
                mma_f16(acc[mt][nt], ah, bl[nt]);   // hi*lo
                mma_f16(acc[mt][nt], al, bh[nt]);   // lo*hi
            }
        }
        if (t + 1 < ntiles) storeS(buf ^ 1);
        __syncthreads();
    }

#pragma unroll
    for (int mt = 0; mt < 4; mt++) {
        int rbase = row0 + warp_m * 64 + mt * 16 + grp;
#pragma unroll
        for (int nt = 0; nt < 4; nt++) {
            int cbase = col0 + warp_n * 32 + nt * 8 + 2 * qid;
#pragma unroll
            for (int half = 0; half < 2; half++) {
                int r = rbase + half * 8;
                if (r >= M) continue;
#pragma unroll
                for (int e = 0; e < 2; e++) {
                    int c = cbase + e;
                    float v = acc[mt][nt][half * 2 + e];
                    if (EPI == 1 || EPI == 2) v += bias[c];
                    if (EPI == 1) v = v > 0.0f ? v : expm1f(v);
                    C[(size_t)r * N + c] = v;
                }
            }
        }
    }
}

// ---------------- host orchestration ---------------------------------------
static inline int cdiv(long long a, long long b) { return (int)((a + b - 1) / b); }

extern "C" void kernel_launch(void* const* d_in, const int* in_sizes, int n_in,
                              void* d_out, int out_size) {
    const float* x    = (const float*)d_in[0];
    const int*   y    = (const int*)  d_in[1];
    const int*   adj  = (const int*)  d_in[3];
    const int*   idxl = (const int*)  d_in[4];
    const float* W0  = (const float*)d_in[6];
    const float* b0  = (const float*)d_in[7];
    const float* W1  = (const float*)d_in[8];
    const float* b1  = (const float*)d_in[9];
    const float* W2  = (const float*)d_in[10];
    const float* b2  = (const float*)d_in[11];
    const float* Wm0 = (const float*)d_in[12];
    const float* bm0 = (const float*)d_in[13];
    const float* Wm1 = (const float*)d_in[14];
    const float* bm1 = (const float*)d_in[15];

    int N = in_sizes[1];
    int E = in_sizes[3] / 2;
    int L = in_sizes[4];
    float* out = (float*)d_out;

    float *p_t, *p_h, *p_m;
    cudaGetSymbolAddress((void**)&p_t, g_t);
    cudaGetSymbolAddress((void**)&p_h, g_h);
    cudaGetSymbolAddress((void**)&p_m, g_m);

    const int TB = 256;

    // CSR build
    k_zero_cnt<<<cdiv(N, TB), TB>>>(N);
    k_count<<<cdiv(E, TB), TB>>>(adj, E);
    k_scan<<<1, 1024>>>(N, E);
    k_dinv<<<cdiv(N, TB), TB>>>(N);
    k_fill<<<cdiv(E, TB), TB>>>(adj, E);

    // labels
    k_lab_init<<<cdiv(N, TB), TB>>>(N);
    k_lab_set<<<cdiv(L, TB), TB>>>(idxl, y, L);

    dim3 gridH(CNHID / 128, cdiv(N, 128));
    long long nwcell = (long long)N * 32;

    // GCN layer 1
    k_tc_gemm<128, 0><<<gridH, 256>>>(x, W0, p_t, nullptr, N, CNHID, CNFEAT);
    k_lab_add<<<cdiv(nwcell, TB), TB>>>(W0, N);
    k_agg_csr<<<cdiv(nwcell, TB), TB>>>(p_t, p_h, b0, N);

    // GCN layer 2
    k_tc_gemm<128, 0><<<gridH, 256>>>(p_h, W1, p_t, nullptr, N, CNHID, CNHID);
    k_agg_csr<<<cdiv(nwcell, TB), TB>>>(p_t, p_h, b1, N);

    // GCN layer 3
    k_tc_gemm<128, 0><<<gridH, 256>>>(p_h, W2, p_t, nullptr, N, CNHID, CNHID);
    k_agg_csr<<<cdiv(nwcell, TB), TB>>>(p_t, p_h, b2, N);

    // MLP head
    {
        dim3 grid(CHID2 / 128, cdiv(N, 128));
        k_tc_gemm<128, 1><<<grid, 256>>>(p_h, Wm0, p_m, bm0, N, CHID2, CNHID);
    }
    {
        dim3 grid(CNLABEL / 64, cdiv(N, 128));
        k_tc_gemm<64, 2><<<grid, 128>>>(p_m, Wm1, out, bm1, N, CNLABEL, CHID2);
    }

    // log_softmax
    k_logsoftmax64<<<cdiv(nwcell, TB), TB>>>(out, N);
}

// round 6
// speedup vs baseline: 3.2055x; 1.1069x over previous
#include <cuda_runtime.h>
#include <cuda_fp16.h>
#include <cstdint>
#include <math.h>

// Problem constants (fixed shapes)
#define CN      100000
#define CE      1600000
#define CNFEAT  512
#define CNLABEL 64
#define CNHID   256
#define CHID2   512

// ---------------- scratch (device globals) ----------------------------------
__device__ float  g_t   [(size_t)CN * CNHID];   // GEMM output (fp32) for aggregation
__device__ __half g_h_hi[(size_t)CN * CNHID];   // hidden state split halves
__device__ __half g_h_lo[(size_t)CN * CNHID];
__device__ __half g_m_hi[(size_t)CN * CHID2];   // MLP hidden split halves
__device__ __half g_m_lo[(size_t)CN * CHID2];
__device__ __half g_x_hi[(size_t)CN * CNFEAT];  // input features split halves
__device__ __half g_x_lo[(size_t)CN * CNFEAT];
__device__ __half g_wt_hi[512 * 512];           // transposed weight (K-major) halves
__device__ __half g_wt_lo[512 * 512];
__device__ float  g_dinv[CN];
__device__ int    g_cnt[CN];
__device__ int    g_rowptr[CN + 1];
__device__ int    g_cursor[CN];
__device__ int    g_src[CE];
__device__ float  g_w[CE];
__device__ int    g_lab[CN];

// ---------------- CSR build --------------------------------------------------
__global__ void k_zero_cnt(int n) {
    int i = blockIdx.x * blockDim.x + threadIdx.x;
    if (i < n) g_cnt[i] = 0;
}
__global__ void k_count(const int* __restrict__ adj, int E) {
    int e = blockIdx.x * blockDim.x + threadIdx.x;
    if (e >= E) return;
    atomicAdd(&g_cnt[adj[E + e]], 1);
}
__global__ void k_scan(int n, int E) {
    __shared__ int bs[1024];
    int tid = threadIdx.x;
    int chunk = (n + 1023) / 1024;
    int lo = tid * chunk;
    int hi = lo + chunk; if (hi > n) hi = n; if (lo > n) lo = n;
    int s = 0;
    for (int i = lo; i < hi; i++) s += g_cnt[i];
    int mysum = s;
    bs[tid] = s;
    __syncthreads();
    for (int d = 1; d < 1024; d <<= 1) {
        int v = (tid >= d) ? bs[tid - d] : 0;
        __syncthreads();
        bs[tid] += v;
        __syncthreads();
    }
    int off = bs[tid] - mysum;
    for (int i = lo; i < hi; i++) {
        g_rowptr[i] = off;
        g_cursor[i] = off;
        off += g_cnt[i];
    }
    if (tid == 1023) g_rowptr[n] = E;
}
__global__ void k_dinv(int n) {
    int i = blockIdx.x * blockDim.x + threadIdx.x;
    if (i < n) g_dinv[i] = rsqrtf((float)g_cnt[i] + 2.0f);
}
__global__ void k_fill(const int* __restrict__ adj, int E) {
    int e = blockIdx.x * blockDim.x + threadIdx.x;
    if (e >= E) return;
    int src = adj[e];
    int dst = adj[E + e];
    int pos = atomicAdd(&g_cursor[dst], 1);
    g_src[pos] = src;
    g_w[pos] = g_dinv[src] * g_dinv[dst];
}

// ---------------- labels ------------------------------------------------------
__global__ void k_lab_init(int n) {
    int i = blockIdx.x * blockDim.x + threadIdx.x;
    if (i < n) g_lab[i] = -1;
}
__global__ void k_lab_set(const int* __restrict__ idxl, const int* __restrict__ y, int L) {
    int t = blockIdx.x * blockDim.x + threadIdx.x;
    if (t >= L) return;
    int node = idxl[t];
    g_lab[node] = y[node];
}
__global__ void k_lab_add(const float* __restrict__ W0, int n) {
    int gt = blockIdx.x * blockDim.x + threadIdx.x;
    int warp = gt >> 5, lane = gt & 31;
    if (warp >= n) return;
    int lab = g_lab[warp];
    if (lab < 0) return;
    const float* wrow = W0 + (size_t)(CNFEAT + lab) * CNHID;
    float* trow = g_t + (size_t)warp * CNHID;
#pragma unroll
    for (int k = 0; k < CNHID / 32; k++)
        trow[k * 32 + lane] += wrow[k * 32 + lane];
}

// ---------------- split helpers ------------------------------------------------
__device__ __forceinline__ void split1(float v, __half& h, __half& l) {
    h = __float2half_rn(v);
    l = __float2half_rn(v - __half2float(h));
}

__global__ void k_split(const float* __restrict__ X, __half* __restrict__ H,
                        __half* __restrict__ L, long long nq) {
    long long i = (long long)blockIdx.x * blockDim.x + threadIdx.x;
    if (i >= nq) return;
    float4 v = ((const float4*)X)[i];
    __half2 h0 = __floats2half2_rn(v.x, v.y), h1 = __floats2half2_rn(v.z, v.w);
    float2 f0 = __half22float2(h0), f1 = __half22float2(h1);
    __half2 l0 = __floats2half2_rn(v.x - f0.x, v.y - f0.y);
    __half2 l1 = __floats2half2_rn(v.z - f1.x, v.w - f1.y);
    ((__half2*)H)[2 * i] = h0; ((__half2*)H)[2 * i + 1] = h1;
    ((__half2*)L)[2 * i] = l0; ((__half2*)L)[2 * i + 1] = l1;
}

// transpose + split weight: Wt[n][k] = W[k][n]
__global__ void k_wt(const float* __restrict__ W, int K, int N) {
    int idx = blockIdx.x * blockDim.x + threadIdx.x;
    if (idx >= N * K) return;
    int n = idx / K, k = idx % K;
    float v = W[(size_t)k * N + n];
    __half h, l;
    split1(v, h, l);
    g_wt_hi[idx] = h;
    g_wt_lo[idx] = l;
}

// ---------------- fused CSR aggregation: h(split) = relu(bias + self + edges) --
__global__ void __launch_bounds__(256)
k_agg_csr(const float* __restrict__ t, __half* __restrict__ Oh, __half* __restrict__ Ol,
          const float* __restrict__ bias, int n) {
    int warp = (blockIdx.x * blockDim.x + threadIdx.x) >> 5;
    int lane = threadIdx.x & 31;
    if (warp >= n) return;
    int beg = g_rowptr[warp];
    int end = g_rowptr[warp + 1];
    const float4* ti = (const float4*)(t + (size_t)warp * CNHID);
    const float4* bi = (const float4*)bias;
    float d = g_dinv[warp];
    float sw = 2.0f * d * d;

    float4 a0 = bi[lane], a1 = bi[32 + lane];
    float4 s0 = ti[lane], s1 = ti[32 + lane];
    a0.x += sw * s0.x; a0.y += sw * s0.y; a0.z += sw * s0.z; a0.w += sw * s0.w;
    a1.x += sw * s1.x; a1.y += sw * s1.y; a1.z += sw * s1.z; a1.w += sw * s1.w;

    int e = beg;
    for (; e + 1 < end; e += 2) {
        int sA = g_src[e], sB = g_src[e + 1];
        float wA = g_w[e], wB = g_w[e + 1];
        const float4* tA = (const float4*)(t + (size_t)sA * CNHID);
        const float4* tB = (const float4*)(t + (size_t)sB * CNHID);
        float4 vA0 = tA[lane], vA1 = tA[32 + lane];
        float4 vB0 = tB[lane], vB1 = tB[32 + lane];
        a0.x = fmaf(wA, vA0.x, a0.x); a0.y = fmaf(wA, vA0.y, a0.y);
        a0.z = fmaf(wA, vA0.z, a0.z); a0.w = fmaf(wA, vA0.w, a0.w);
        a1.x = fmaf(wA, vA1.x, a1.x); a1.y = fmaf(wA, vA1.y, a1.y);
        a1.z = fmaf(wA, vA1.z, a1.z); a1.w = fmaf(wA, vA1.w, a1.w);
        a0.x = fmaf(wB, vB0.x, a0.x); a0.y = fmaf(wB, vB0.y, a0.y);
        a0.z = fmaf(wB, vB0.z, a0.z); a0.w = fmaf(wB, vB0.w, a0.w);
        a1.x = fmaf(wB, vB1.x, a1.x); a1.y = fmaf(wB, vB1.y, a1.y);
        a1.z = fmaf(wB, vB1.z, a1.z); a1.w = fmaf(wB, vB1.w, a1.w);
    }
    if (e < end) {
        int sA = g_src[e];
        float wA = g_w[e];
        const float4* tA = (const float4*)(t + (size_t)sA * CNHID);
        float4 vA0 = tA[lane], vA1 = tA[32 + lane];
        a0.x = fmaf(wA, vA0.x, a0.x); a0.y = fmaf(wA, vA0.y, a0.y);
        a0.z = fmaf(wA, vA0.z, a0.z); a0.w = fmaf(wA, vA0.w, a0.w);
        a1.x = fmaf(wA, vA1.x, a1.x); a1.y = fmaf(wA, vA1.y, a1.y);
        a1.z = fmaf(wA, vA1.z, a1.z); a1.w = fmaf(wA, vA1.w, a1.w);
    }

    float v[8] = {fmaxf(a0.x, 0.f), fmaxf(a0.y, 0.f), fmaxf(a0.z, 0.f), fmaxf(a0.w, 0.f),
                  fmaxf(a1.x, 0.f), fmaxf(a1.y, 0.f), fmaxf(a1.z, 0.f), fmaxf(a1.w, 0.f)};
    __align__(8) __half hb[8], lb[8];
#pragma unroll
    for (int k = 0; k < 8; k++) split1(v[k], hb[k], lb[k]);
    size_t base = (size_t)warp * CNHID + 4 * lane;
    *(uint2*)&Oh[base]       = *(uint2*)&hb[0];
    *(uint2*)&Oh[base + 128] = *(uint2*)&hb[4];
    *(uint2*)&Ol[base]       = *(uint2*)&lb[0];
    *(uint2*)&Ol[base + 128] = *(uint2*)&lb[4];
}

// ---------------- log_softmax --------------------------------------------------
__global__ void k_logsoftmax64(float* __restrict__ out, int n) {
    int gt = blockIdx.x * blockDim.x + threadIdx.x;
    int warp = gt >> 5, lane = gt & 31;
    if (warp >= n) return;
    float* r = out + (size_t)warp * 64;
    float v0 = r[lane], v1 = r[lane + 32];
    float m = fmaxf(v0, v1);
#pragma unroll
    for (int o = 16; o; o >>= 1) m = fmaxf(m, __shfl_xor_sync(0xffffffffu, m, o));
    float s = expf(v0 - m) + expf(v1 - m);
#pragma unroll
    for (int o = 16; o; o >>= 1) s += __shfl_xor_sync(0xffffffffu, s, o);
    float l = m + logf(s);
    r[lane] = v0 - l;
    r[lane + 32] = v1 - l;
}

// ---------------- pre-split FP16 tensor-core GEMM ------------------------------
// C[M,N] = A[M,K] @ B[K,N]: A as (hi,lo) f16 [M][K], B as transposed (hi,lo)
// f16 [N][K]. 3-term product hi*hi + hi*lo + lo*hi, fp32 accumulate.
// BM=128, BK=32, BN in {64,128}. cp.async double-buffered. No cvt in mainloop.
// EPI: 0 -> C fp32 | 1 -> bias+ELU, split to (Oh,Ol) | 2 -> bias, C fp32

__device__ __forceinline__ void mma_f16(float* c, const uint32_t* a, const uint32_t* b) {
    asm volatile(
        "mma.sync.aligned.m16n8k16.row.col.f32.f16.f16.f32 "
        "{%0,%1,%2,%3}, {%4,%5,%6,%7}, {%8,%9}, {%0,%1,%2,%3};\n"
        : "+f"(c[0]), "+f"(c[1]), "+f"(c[2]), "+f"(c[3])
        : "r"(a[0]), "r"(a[1]), "r"(a[2]), "r"(a[3]), "r"(b[0]), "r"(b[1]));
}

__device__ __forceinline__ uint32_t s2u(const void* p) {
    uint32_t a;
    asm("{ .reg .u64 t; cvta.to.shared.u64 t, %1; cvt.u32.u64 %0, t; }" : "=r"(a) : "l"(p));
    return a;
}
__device__ __forceinline__ void cpa16(uint32_t dst, const void* src, bool pred) {
    asm volatile("cp.async.cg.shared.global [%0], [%1], 16, %2;"
                 :: "r"(dst), "l"(src), "r"(pred ? 16 : 0) : "memory");
}
__device__ __forceinline__ void cpa_commit() {
    asm volatile("cp.async.commit_group;" ::: "memory");
}
__device__ __forceinline__ void cpa_wait0() {
    asm volatile("cp.async.wait_group 0;" ::: "memory");
}

template <int BN, int EPI>
__global__ void __launch_bounds__(256)
k_hgemm(const __half* __restrict__ Ah, const __half* __restrict__ Al,
        const __half* __restrict__ Bh, const __half* __restrict__ Bl,
        float* __restrict__ C, const float* __restrict__ bias,
        __half* __restrict__ Oh, __half* __restrict__ Ol,
        int M, int N, int K) {
    // SMEM rows: 32 halves data, 80-byte stride (bank-conflict-free: 20r+q mod 32)
    constexpr int RSTR  = 80;
    constexpr int ATILE = 128 * RSTR;           // bytes per A hi (or lo) tile
    constexpr int ABUF  = 2 * ATILE;            // hi + lo
    constexpr int BTILE = BN * RSTR;
    constexpr int BBUF  = 2 * BTILE;
    constexpr int OFFB  = 2 * ABUF;             // after 2 A buffers
    constexpr int NWN   = BN / 32;              // warps along n
    constexpr int MT    = (128 / (8 / NWN)) / 16;  // m16 tiles per warp

    extern __shared__ char smem[];
    const uint32_t sb = s2u(smem);
    const int tid = threadIdx.x;
    const int wid = tid >> 5, lane = tid & 31;
    const int grp = lane >> 2, qid = lane & 3;
    const int warp_m = wid / NWN, warp_n = wid % NWN;
    const int row0 = blockIdx.y * 128;
    const int col0 = blockIdx.x * BN;

    float acc[MT][4][4];
#pragma unroll
    for (int i = 0; i < MT; i++)
#pragma unroll
        for (int j = 0; j < 4; j++)
#pragma unroll
            for (int c = 0; c < 4; c++) acc[i][j][c] = 0.0f;

    auto loadSlab = [&](int s, int b) {
        int k0 = s * 32;
        // A: 128 rows x 64B = 512 chunks of 16B ; 2 per thread
#pragma unroll
        for (int i = 0; i < 2; i++) {
            int c = tid + i * 256;
            int r = c >> 2, p = c & 3;
            bool ok = (row0 + r) < M;
            int rr = ok ? (row0 + r) : (M - 1);
            size_t g = (size_t)rr * K + k0 + p * 8;
            uint32_t dst = sb + b * ABUF + r * RSTR + p * 16;
            cpa16(dst,         Ah + g, ok);
            cpa16(dst + ATILE, Al + g, ok);
        }
        // B: BN rows x 64B = BN*4 chunks ; BN/64 per thread
#pragma unroll
        for (int i = 0; i < BN / 64; i++) {
            int c = tid + i * 256;
            int r = c >> 2, p = c & 3;
            size_t g = (size_t)(col0 + r) * K + k0 + p * 8;
            uint32_t dst = sb + OFFB + b * BBUF + r * RSTR + p * 16;
            cpa16(dst,         Bh + g, true);
            cpa16(dst + BTILE, Bl + g, true);
        }
        cpa_commit();
    };

    auto computeSlab = [&](int b) {
        const char* aBase = smem + b * ABUF;
        const char* bBase = smem + OFFB + b * BBUF;
#pragma unroll
        for (int ks = 0; ks < 2; ks++) {
            const int kb = ks * 32 + qid * 4;   // byte offset within row
            uint32_t bh[4][2], bl[4][2];
#pragma unroll
            for (int nt = 0; nt < 4; nt++) {
                int n = warp_n * 32 + nt * 8 + grp;
                const char* p = bBase + n * RSTR + kb;
                bh[nt][0] = *(const uint32_t*)(p);
                bh[nt][1] = *(const uint32_t*)(p + 16);
                bl[nt][0] = *(const uint32_t*)(p + BTILE);
                bl[nt][1] = *(const uint32_t*)(p + BTILE + 16);
            }
#pragma unroll
            for (int mt = 0; mt < MT; mt++) {
                int r = warp_m * (MT * 16) + mt * 16 + grp;
                const char* p = aBase + r * RSTR + kb;
                uint32_t ah[4], al[4];
                ah[0] = *(const uint32_t*)(p);
                ah[1] = *(const uint32_t*)(p + 8 * RSTR);
                ah[2] = *(const uint32_t*)(p + 16);
                ah[3] = *(const uint32_t*)(p + 8 * RSTR + 16);
                al[0] = *(const uint32_t*)(p + ATILE);
                al[1] = *(const uint32_t*)(p + ATILE + 8 * RSTR);
                al[2] = *(const uint32_t*)(p + ATILE + 16);
                al[3] = *(const uint32_t*)(p + ATILE + 8 * RSTR + 16);
#pragma unroll
                for (int nt = 0; nt < 4; nt++) {
                    mma_f16(acc[mt][nt], ah, bh[nt]);   // hi*hi
                    mma_f16(acc[mt][nt], ah, bl[nt]);   // hi*lo
                    mma_f16(acc[mt][nt], al, bh[nt]);   // lo*hi
                }
            }
        }
    };

    const int ns = K / 32;
    loadSlab(0, 0);
    cpa_wait0();
    __syncthreads();
    for (int s = 0; s < ns; s++) {
        int b = s & 1;
        if (s + 1 < ns) loadSlab(s + 1, b ^ 1);
        computeSlab(b);
        if (s + 1 < ns) {
            cpa_wait0();
            __syncthreads();
        }
    }

    // ---- epilogue ----
#pragma unroll
    for (int mt = 0; mt < MT; mt++) {
        int rbase = row0 + warp_m * (MT * 16) + mt * 16 + grp;
#pragma unroll
        for (int nt = 0; nt < 4; nt++) {
            int cb = col0 + warp_n * 32 + nt * 8 + 2 * qid;
#pragma unroll
            for (int half = 0; half < 2; half++) {
                int r = rbase + half * 8;
                if (r >= M) continue;
                float v0 = acc[mt][nt][half * 2 + 0];
                float v1 = acc[mt][nt][half * 2 + 1];
                if (EPI >= 1) { v0 += bias[cb]; v1 += bias[cb + 1]; }
                if (EPI == 1) {
                    v0 = v0 > 0.0f ? v0 : expm1f(v0);
                    v1 = v1 > 0.0f ? v1 : expm1f(v1);
                }
                if (EPI == 1) {
                    __half h0, l0, h1, l1;
                    split1(v0, h0, l0);
                    split1(v1, h1, l1);
                    __half2 hh = __halves2half2(h0, h1);
                    __half2 ll = __halves2half2(l0, l1);
                    size_t base = (size_t)r * N + cb;
                    *(__half2*)&Oh[base] = hh;
                    *(__half2*)&Ol[base] = ll;
                } else {
                    *(float2*)&C[(size_t)r * N + cb] = make_float2(v0, v1);
                }
            }
        }
    }
}

// ---------------- host orchestration ---------------------------------------
static inline int cdiv(long long a, long long b) { return (int)((a + b - 1) / b); }

extern "C" void kernel_launch(void* const* d_in, const int* in_sizes, int n_in,
                              void* d_out, int out_size) {
    const float* x    = (const float*)d_in[0];
    const int*   y    = (const int*)  d_in[1];
    const int*   adj  = (const int*)  d_in[3];
    const int*   idxl = (const int*)  d_in[4];
    const float* W0  = (const float*)d_in[6];
    const float* b0  = (const float*)d_in[7];
    const float* W1  = (const float*)d_in[8];
    const float* b1  = (const float*)d_in[9];
    const float* W2  = (const float*)d_in[10];
    const float* b2  = (const float*)d_in[11];
    const float* Wm0 = (const float*)d_in[12];
    const float* bm0 = (const float*)d_in[13];
    const float* Wm1 = (const float*)d_in[14];
    const float* bm1 = (const float*)d_in[15];

    int N = in_sizes[1];
    int E = in_sizes[3] / 2;
    int L = in_sizes[4];
    float* out = (float*)d_out;

    float *p_t;
    __half *p_hh, *p_hl, *p_mh, *p_ml, *p_xh, *p_xl, *p_wh, *p_wl;
    cudaGetSymbolAddress((void**)&p_t,  g_t);
    cudaGetSymbolAddress((void**)&p_hh, g_h_hi);
    cudaGetSymbolAddress((void**)&p_hl, g_h_lo);
    cudaGetSymbolAddress((void**)&p_mh, g_m_hi);
    cudaGetSymbolAddress((void**)&p_ml, g_m_lo);
    cudaGetSymbolAddress((void**)&p_xh, g_x_hi);
    cudaGetSymbolAddress((void**)&p_xl, g_x_lo);
    cudaGetSymbolAddress((void**)&p_wh, g_wt_hi);
    cudaGetSymbolAddress((void**)&p_wl, g_wt_lo);

    const int TB = 256;
    // smem: A 2buf*2*128*80 = 40960 ; B 2buf*2*BN*80
    const int SMEM128 = 40960 + 2 * 2 * 128 * 80;   // 81920
    const int SMEM64  = 40960 + 2 * 2 * 64 * 80;    // 61440
    cudaFuncSetAttribute(k_hgemm<128, 0>, cudaFuncAttributeMaxDynamicSharedMemorySize, SMEM128);
    cudaFuncSetAttribute(k_hgemm<128, 1>, cudaFuncAttributeMaxDynamicSharedMemorySize, SMEM128);
    cudaFuncSetAttribute(k_hgemm<64, 2>,  cudaFuncAttributeMaxDynamicSharedMemorySize, SMEM64);

    // CSR build
    k_zero_cnt<<<cdiv(N, TB), TB>>>(N);
    k_count<<<cdiv(E, TB), TB>>>(adj, E);
    k_scan<<<1, 1024>>>(N, E);
    k_dinv<<<cdiv(N, TB), TB>>>(N);
    k_fill<<<cdiv(E, TB), TB>>>(adj, E);

    // labels
    k_lab_init<<<cdiv(N, TB), TB>>>(N);
    k_lab_set<<<cdiv(L, TB), TB>>>(idxl, y, L);

    // split input features
    long long xq = (long long)N * CNFEAT / 4;
    k_split<<<cdiv(xq, TB), TB>>>(x, p_xh, p_xl, xq);

    long long nwcell = (long long)N * 32;
    int gy = cdiv(N, 128);

    // ---- GCN layer 1: t = x @ W0[:512]; +labels; aggregate ----
    k_wt<<<cdiv(256 * 512, TB), TB>>>(W0, 512, 256);
    k_hgemm<128, 0><<<dim3(2, gy), 256, SMEM128>>>(p_xh, p_xl, p_wh, p_wl,
                                                   p_t, nullptr, nullptr, nullptr,
                                                   N, 256, 512);
    k_lab_add<<<cdiv(nwcell, TB), TB>>>(W0, N);
    k_agg_csr<<<cdiv(nwcell, TB), TB>>>(p_t, p_hh, p_hl, b0, N);

    // ---- GCN layer 2 ----
    k_wt<<<cdiv(256 * 256, TB), TB>>>(W1, 256, 256);
    k_hgemm<128, 0><<<dim3(2, gy), 256, SMEM128>>>(p_hh, p_hl, p_wh, p_wl,
                                                   p_t, nullptr, nullptr, nullptr,
                                                   N, 256, 256);
    k_agg_csr<<<cdiv(nwcell, TB), TB>>>(p_t, p_hh, p_hl, b1, N);

    // ---- GCN layer 3 ----
    k_wt<<<cdiv(256 * 256, TB), TB>>>(W2, 256, 256);
    k_hgemm<128, 0><<<dim3(2, gy), 256, SMEM128>>>(p_hh, p_hl, p_wh, p_wl,
                                                   p_t, nullptr, nullptr, nullptr,
                                                   N, 256, 256);
    k_agg_csr<<<cdiv(nwcell, TB), TB>>>(p_t, p_hh, p_hl, b2, N);

    // ---- MLP head: m = elu(h @ Wm0 + bm0) (split) ----
    k_wt<<<cdiv(512 * 256, TB), TB>>>(Wm0, 256, 512);
    k_hgemm<128, 1><<<dim3(4, gy), 256, SMEM128>>>(p_hh, p_hl, p_wh, p_wl,
                                                   nullptr, bm0, p_mh, p_ml,
                                                   N, 512, 256);
    // ---- logits = m @ Wm1 + bm1 ----
    k_wt<<<cdiv(64 * 512, TB), TB>>>(Wm1, 512, 64);
    k_hgemm<64, 2><<<dim3(1, gy), 256, SMEM64>>>(p_mh, p_ml, p_wh, p_wl,
                                                 out, bm1, nullptr, nullptr,
                                                 N, 64, 512);

    // ---- log_softmax ----
    k_logsoftmax64<<<cdiv(nwcell, TB), TB>>>(out, N);
}

// round 7
// speedup vs baseline: 3.4592x; 1.0791x over previous
#include <cuda_runtime.h>
#include <cuda_fp16.h>
#include <cstdint>
#include <math.h>

// Problem constants (fixed shapes)
#define CN      100000
#define CE      1600000
#define CNFEAT  512
#define CNLABEL 64
#define CNHID   256
#define CHID2   512

// ---------------- scratch (device globals) ----------------------------------
__device__ float  g_t   [(size_t)CN * CNHID];
__device__ __half g_h_hi[(size_t)CN * CNHID];
__device__ __half g_h_lo[(size_t)CN * CNHID];
__device__ __half g_m_hi[(size_t)CN * CHID2];
__device__ __half g_m_lo[(size_t)CN * CHID2];
__device__ __half g_x_hi[(size_t)CN * CNFEAT];
__device__ __half g_x_lo[(size_t)CN * CNFEAT];
// per-layer transposed split weights (K-major [n][k])
__device__ __half g_w0t_hi[256 * 512], g_w0t_lo[256 * 512];
__device__ __half g_w1t_hi[256 * 256], g_w1t_lo[256 * 256];
__device__ __half g_w2t_hi[256 * 256], g_w2t_lo[256 * 256];
__device__ __half g_wm0t_hi[512 * 256], g_wm0t_lo[512 * 256];
__device__ __half g_wm1t_hi[64 * 512],  g_wm1t_lo[64 * 512];
__device__ float  g_dinv[CN];
__device__ int    g_cnt[CN];
__device__ int    g_rowptr[CN + 1];
__device__ int    g_cursor[CN];
__device__ int    g_src[CE];
__device__ float  g_w[CE];
__device__ int    g_lab[CN];

// ---------------- CSR build --------------------------------------------------
__global__ void k_zero_cnt(int n) {
    int i = blockIdx.x * blockDim.x + threadIdx.x;
    if (i < n) g_cnt[i] = 0;
}
__global__ void k_count(const int* __restrict__ adj, int E) {
    int e = blockIdx.x * blockDim.x + threadIdx.x;
    if (e >= E) return;
    atomicAdd(&g_cnt[adj[E + e]], 1);
}
__global__ void k_scan(int n, int E) {
    __shared__ int bs[1024];
    int tid = threadIdx.x;
    int chunk = (n + 1023) / 1024;
    int lo = tid * chunk;
    int hi = lo + chunk; if (hi > n) hi = n; if (lo > n) lo = n;
    int s = 0;
    for (int i = lo; i < hi; i++) s += g_cnt[i];
    int mysum = s;
    bs[tid] = s;
    __syncthreads();
    for (int d = 1; d < 1024; d <<= 1) {
        int v = (tid >= d) ? bs[tid - d] : 0;
        __syncthreads();
        bs[tid] += v;
        __syncthreads();
    }
    int off = bs[tid] - mysum;
    for (int i = lo; i < hi; i++) {
        g_rowptr[i] = off;
        g_cursor[i] = off;
        off += g_cnt[i];
    }
    if (tid == 1023) g_rowptr[n] = E;
}
__global__ void k_dinv(int n) {
    int i = blockIdx.x * blockDim.x + threadIdx.x;
    if (i < n) g_dinv[i] = rsqrtf((float)g_cnt[i] + 2.0f);
}
__global__ void k_fill(const int* __restrict__ adj, int E) {
    int e = blockIdx.x * blockDim.x + threadIdx.x;
    if (e >= E) return;
    int src = adj[e];
    int dst = adj[E + e];
    int pos = atomicAdd(&g_cursor[dst], 1);
    g_src[pos] = src;
    g_w[pos] = g_dinv[src] * g_dinv[dst];
}

// ---------------- labels ------------------------------------------------------
__global__ void k_lab_init(int n) {
    int i = blockIdx.x * blockDim.x + threadIdx.x;
    if (i < n) g_lab[i] = -1;
}
__global__ void k_lab_set(const int* __restrict__ idxl, const int* __restrict__ y, int L) {
    int t = blockIdx.x * blockDim.x + threadIdx.x;
    if (t >= L) return;
    int node = idxl[t];
    g_lab[node] = y[node];
}
__global__ void k_lab_add(const float* __restrict__ W0, int n) {
    int gt = blockIdx.x * blockDim.x + threadIdx.x;
    int warp = gt >> 5, lane = gt & 31;
    if (warp >= n) return;
    int lab = g_lab[warp];
    if (lab < 0) return;
    const float* wrow = W0 + (size_t)(CNFEAT + lab) * CNHID;
    float* trow = g_t + (size_t)warp * CNHID;
#pragma unroll
    for (int k = 0; k < CNHID / 32; k++)
        trow[k * 32 + lane] += wrow[k * 32 + lane];
}

// ---------------- split helpers ------------------------------------------------
__device__ __forceinline__ void split1(float v, __half& h, __half& l) {
    h = __float2half_rn(v);
    l = __float2half_rn(v - __half2float(h));
}

__global__ void k_split(const float* __restrict__ X, __half* __restrict__ H,
                        __half* __restrict__ L, long long nq) {
    long long i = (long long)blockIdx.x * blockDim.x + threadIdx.x;
    if (i >= nq) return;
    float4 v = ((const float4*)X)[i];
    __half2 h0 = __floats2half2_rn(v.x, v.y), h1 = __floats2half2_rn(v.z, v.w);
    float2 f0 = __half22float2(h0), f1 = __half22float2(h1);
    __half2 l0 = __floats2half2_rn(v.x - f0.x, v.y - f0.y);
    __half2 l1 = __floats2half2_rn(v.z - f1.x, v.w - f1.y);
    ((__half2*)H)[2 * i] = h0; ((__half2*)H)[2 * i + 1] = h1;
    ((__half2*)L)[2 * i] = l0; ((__half2*)L)[2 * i + 1] = l1;
}

// transpose + split weight: Wt[n][k] = W[k][n]
__global__ void k_wt(const float* __restrict__ W, __half* __restrict__ TH,
                     __half* __restrict__ TL, int K, int N) {
    int idx = blockIdx.x * blockDim.x + threadIdx.x;
    if (idx >= N * K) return;
    int n = idx / K, k = idx % K;
    float v = W[(size_t)k * N + n];
    __half h, l;
    split1(v, h, l);
    TH[idx] = h;
    TL[idx] = l;
}

// ---------------- fused CSR aggregation --------------------------------------
__global__ void __launch_bounds__(256)
k_agg_csr(const float* __restrict__ t, __half* __restrict__ Oh, __half* __restrict__ Ol,
          const float* __restrict__ bias, int n) {
    int warp = (blockIdx.x * blockDim.x + threadIdx.x) >> 5;
    int lane = threadIdx.x & 31;
    if (warp >= n) return;
    int beg = g_rowptr[warp];
    int end = g_rowptr[warp + 1];
    const float4* ti = (const float4*)(t + (size_t)warp * CNHID);
    const float4* bi = (const float4*)bias;
    float d = g_dinv[warp];
    float sw = 2.0f * d * d;

    float4 a0 = bi[lane], a1 = bi[32 + lane];
    float4 s0 = ti[lane], s1 = ti[32 + lane];
    a0.x += sw * s0.x; a0.y += sw * s0.y; a0.z += sw * s0.z; a0.w += sw * s0.w;
    a1.x += sw * s1.x; a1.y += sw * s1.y; a1.z += sw * s1.z; a1.w += sw * s1.w;

    int e = beg;
    for (; e + 1 < end; e += 2) {
        int sA = g_src[e], sB = g_src[e + 1];
        float wA = g_w[e], wB = g_w[e + 1];
        const float4* tA = (const float4*)(t + (size_t)sA * CNHID);
        const float4* tB = (const float4*)(t + (size_t)sB * CNHID);
        float4 vA0 = tA[lane], vA1 = tA[32 + lane];
        float4 vB0 = tB[lane], vB1 = tB[32 + lane];
        a0.x = fmaf(wA, vA0.x, a0.x); a0.y = fmaf(wA, vA0.y, a0.y);
        a0.z = fmaf(wA, vA0.z, a0.z); a0.w = fmaf(wA, vA0.w, a0.w);
        a1.x = fmaf(wA, vA1.x, a1.x); a1.y = fmaf(wA, vA1.y, a1.y);
        a1.z = fmaf(wA, vA1.z, a1.z); a1.w = fmaf(wA, vA1.w, a1.w);
        a0.x = fmaf(wB, vB0.x, a0.x); a0.y = fmaf(wB, vB0.y, a0.y);
        a0.z = fmaf(wB, vB0.z, a0.z); a0.w = fmaf(wB, vB0.w, a0.w);
        a1.x = fmaf(wB, vB1.x, a1.x); a1.y = fmaf(wB, vB1.y, a1.y);
        a1.z = fmaf(wB, vB1.z, a1.z); a1.w = fmaf(wB, vB1.w, a1.w);
    }
    if (e < end) {
        int sA = g_src[e];
        float wA = g_w[e];
        const float4* tA = (const float4*)(t + (size_t)sA * CNHID);
        float4 vA0 = tA[lane], vA1 = tA[32 + lane];
        a0.x = fmaf(wA, vA0.x, a0.x); a0.y = fmaf(wA, vA0.y, a0.y);
        a0.z = fmaf(wA, vA0.z, a0.z); a0.w = fmaf(wA, vA0.w, a0.w);
        a1.x = fmaf(wA, vA1.x, a1.x); a1.y = fmaf(wA, vA1.y, a1.y);
        a1.z = fmaf(wA, vA1.z, a1.z); a1.w = fmaf(wA, vA1.w, a1.w);
    }

    float v[8] = {fmaxf(a0.x, 0.f), fmaxf(a0.y, 0.f), fmaxf(a0.z, 0.f), fmaxf(a0.w, 0.f),
                  fmaxf(a1.x, 0.f), fmaxf(a1.y, 0.f), fmaxf(a1.z, 0.f), fmaxf(a1.w, 0.f)};
    __align__(8) __half hb[8], lb[8];
#pragma unroll
    for (int k = 0; k < 8; k++) split1(v[k], hb[k], lb[k]);
    size_t base = (size_t)warp * CNHID + 4 * lane;
    *(uint2*)&Oh[base]       = *(uint2*)&hb[0];
    *(uint2*)&Oh[base + 128] = *(uint2*)&hb[4];
    *(uint2*)&Ol[base]       = *(uint2*)&lb[0];
    *(uint2*)&Ol[base + 128] = *(uint2*)&lb[4];
}

// ---------------- log_softmax --------------------------------------------------
__global__ void k_logsoftmax64(float* __restrict__ out, int n) {
    int gt = blockIdx.x * blockDim.x + threadIdx.x;
    int warp = gt >> 5, lane = gt & 31;
    if (warp >= n) return;
    float* r = out + (size_t)warp * 64;
    float v0 = r[lane], v1 = r[lane + 32];
    float m = fmaxf(v0, v1);
#pragma unroll
    for (int o = 16; o; o >>= 1) m = fmaxf(m, __shfl_xor_sync(0xffffffffu, m, o));
    float s = expf(v0 - m) + expf(v1 - m);
#pragma unroll
    for (int o = 16; o; o >>= 1) s += __shfl_xor_sync(0xffffffffu, s, o);
    float l = m + logf(s);
    r[lane] = v0 - l;
    r[lane + 32] = v1 - l;
}

// ---------------- pre-split FP16 tensor-core GEMM (ldmatrix mainloop) ----------
__device__ __forceinline__ void mma_f16(float* c, const uint32_t* a, const uint32_t* b) {
    asm volatile(
        "mma.sync.aligned.m16n8k16.row.col.f32.f16.f16.f32 "
        "{%0,%1,%2,%3}, {%4,%5,%6,%7}, {%8,%9}, {%0,%1,%2,%3};\n"
        : "+f"(c[0]), "+f"(c[1]), "+f"(c[2]), "+f"(c[3])
        : "r"(a[0]), "r"(a[1]), "r"(a[2]), "r"(a[3]), "r"(b[0]), "r"(b[1]));
}
__device__ __forceinline__ void ldsm4(uint32_t& r0, uint32_t& r1, uint32_t& r2,
                                      uint32_t& r3, uint32_t addr) {
    asm volatile("ldmatrix.sync.aligned.m8n8.x4.shared.b16 {%0,%1,%2,%3}, [%4];"
                 : "=r"(r0), "=r"(r1), "=r"(r2), "=r"(r3) : "r"(addr));
}
__device__ __forceinline__ uint32_t s2u(const void* p) {
    uint32_t a;
    asm("{ .reg .u64 t; cvta.to.shared.u64 t, %1; cvt.u32.u64 %0, t; }" : "=r"(a) : "l"(p));
    return a;
}
__device__ __forceinline__ void cpa16(uint32_t dst, const void* src, bool pred) {
    asm volatile("cp.async.cg.shared.global [%0], [%1], 16, %2;"
                 :: "r"(dst), "l"(src), "r"(pred ? 16 : 0) : "memory");
}
__device__ __forceinline__ void cpa_commit() {
    asm volatile("cp.async.commit_group;" ::: "memory");
}
__device__ __forceinline__ void cpa_wait0() {
    asm volatile("cp.async.wait_group 0;" ::: "memory");
}

// C[M,N] = A @ B; A (hi,lo) f16 [M][K]; B transposed (hi,lo) f16 [N][K].
// BM=128, BK=32. EPI: 0 plain fp32 | 1 bias+ELU -> split (Oh,Ol) | 2 bias fp32
template <int BN, int EPI>
__global__ void __launch_bounds__(256)
k_hgemm(const __half* __restrict__ Ah, const __half* __restrict__ Al,
        const __half* __restrict__ Bh, const __half* __restrict__ Bl,
        float* __restrict__ C, const float* __restrict__ bias,
        __half* __restrict__ Oh, __half* __restrict__ Ol,
        int M, int N, int K) {
    constexpr int RSTR  = 80;                 // 64B data + 16B pad
    constexpr int ATILE = 128 * RSTR;
    constexpr int ABUF  = 2 * ATILE;
    constexpr int BTILE = BN * RSTR;
    constexpr int BBUF  = 2 * BTILE;
    constexpr int OFFB  = 2 * ABUF;
    constexpr int NWN   = BN / 32;
    constexpr int MT    = (128 / (8 / NWN)) / 16;

    extern __shared__ char smem[];
    const uint32_t sb = s2u(smem);
    const int tid = threadIdx.x;
    const int wid = tid >> 5, lane = tid & 31;
    const int grp = lane >> 2, qid = lane & 3;
    const int warp_m = wid / NWN, warp_n = wid % NWN;
    const int row0 = blockIdx.y * 128;
    const int col0 = blockIdx.x * BN;

    // ldmatrix per-lane row/halfsel
    const int lrow = lane & 15;               // matrix row select
    const int lcol = (lane >> 4) * 16;        // 0 or 16 bytes (k chunk)

    float acc[MT][4][4];
#pragma unroll
    for (int i = 0; i < MT; i++)
#pragma unroll
        for (int j = 0; j < 4; j++)
#pragma unroll
            for (int c = 0; c < 4; c++) acc[i][j][c] = 0.0f;

    auto loadSlab = [&](int s, int b) {
        int k0 = s * 32;
#pragma unroll
        for (int i = 0; i < 2; i++) {
            int c = tid + i * 256;
            int r = c >> 2, p = c & 3;
            bool ok = (row0 + r) < M;
            int rr = ok ? (row0 + r) : (M - 1);
            size_t g = (size_t)rr * K + k0 + p * 8;
            uint32_t dst = sb + b * ABUF + r * RSTR + p * 16;
            cpa16(dst,         Ah + g, ok);
            cpa16(dst + ATILE, Al + g, ok);
        }
#pragma unroll
        for (int i = 0; i < BN / 64; i++) {
            int c = tid + i * 256;
            int r = c >> 2, p = c & 3;
            size_t g = (size_t)(col0 + r) * K + k0 + p * 8;
            uint32_t dst = sb + OFFB + b * BBUF + r * RSTR + p * 16;
            cpa16(dst,         Bh + g, true);
            cpa16(dst + BTILE, Bl + g, true);
        }
        cpa_commit();
    };

    auto computeSlab = [&](int b) {
        const uint32_t aB = sb + b * ABUF;
        const uint32_t bB = sb + OFFB + b * BBUF;
#pragma unroll
        for (int ks = 0; ks < 2; ks++) {
            const int kb = ks * 32 + lcol;
            uint32_t bh[4][2], bl[4][2];
#pragma unroll
            for (int p = 0; p < 2; p++) {
                uint32_t addr = bB + (warp_n * 32 + p * 16 + lrow) * RSTR + kb;
                ldsm4(bh[2 * p][0], bh[2 * p + 1][0], bh[2 * p][1], bh[2 * p + 1][1], addr);
                ldsm4(bl[2 * p][0], bl[2 * p + 1][0], bl[2 * p][1], bl[2 * p + 1][1],
                      addr + BTILE);
            }
#pragma unroll
            for (int mt = 0; mt < MT; mt++) {
                uint32_t addr = aB + (warp_m * (MT * 16) + mt * 16 + lrow) * RSTR + kb;
                uint32_t ah[4], al[4];
                ldsm4(ah[0], ah[1], ah[2], ah[3], addr);
                ldsm4(al[0], al[1], al[2], al[3], addr + ATILE);
#pragma unroll
                for (int nt = 0; nt < 4; nt++) {
                    mma_f16(acc[mt][nt], ah, bh[nt]);   // hi*hi
                    mma_f16(acc[mt][nt], ah, bl[nt]);   // hi*lo
                    mma_f16(acc[mt][nt], al, bh[nt]);   // lo*hi
                }
            }
        }
    };

    const int ns = K / 32;
    loadSlab(0, 0);
    cpa_wait0();
    __syncthreads();
    for (int s = 0; s < ns; s++) {
        int b = s & 1;
        if (s + 1 < ns) loadSlab(s + 1, b ^ 1);
        computeSlab(b);
        if (s + 1 < ns) {
            cpa_wait0();
            __syncthreads();
        }
    }

    // ---- epilogue ----
#pragma unroll
    for (int mt = 0; mt < MT; mt++) {
        int rbase = row0 + warp_m * (MT * 16) + mt * 16 + grp;
#pragma unroll
        for (int nt = 0; nt < 4; nt++) {
            int cb = col0 + warp_n * 32 + nt * 8 + 2 * qid;
#pragma unroll
            for (int half = 0; half < 2; half++) {
                int r = rbase + half * 8;
                if (r >= M) continue;
                float v0 = acc[mt][nt][half * 2 + 0];
                float v1 = acc[mt][nt][half * 2 + 1];
                if (EPI >= 1) { v0 += bias[cb]; v1 += bias[cb + 1]; }
                if (EPI == 1) {
                    v0 = v0 > 0.0f ? v0 : expm1f(v0);
                    v1 = v1 > 0.0f ? v1 : expm1f(v1);
                    __half h0, l0, h1, l1;
                    split1(v0, h0, l0);
                    split1(v1, h1, l1);
                    size_t base = (size_t)r * N + cb;
                    *(__half2*)&Oh[base] = __halves2half2(h0, h1);
                    *(__half2*)&Ol[base] = __halves2half2(l0, l1);
                } else {
                    *(float2*)&C[(size_t)r * N + cb] = make_float2(v0, v1);
                }
            }
        }
    }
}

// ---------------- host orchestration ---------------------------------------
static inline int cdiv(long long a, long long b) { return (int)((a + b - 1) / b); }

extern "C" void kernel_launch(void* const* d_in, const int* in_sizes, int n_in,
                              void* d_out, int out_size) {
    const float* x    = (const float*)d_in[0];
    const int*   y    = (const int*)  d_in[1];
    const int*   adj  = (const int*)  d_in[3];
    const int*   idxl = (const int*)  d_in[4];
    const float* W0  = (const float*)d_in[6];
    const float* b0  = (const float*)d_in[7];
    const float* W1  = (const float*)d_in[8];
    const float* b1  = (const float*)d_in[9];
    const float* W2  = (const float*)d_in[10];
    const float* b2  = (const float*)d_in[11];
    const float* Wm0 = (const float*)d_in[12];
    const float* bm0 = (const float*)d_in[13];
    const float* Wm1 = (const float*)d_in[14];
    const float* bm1 = (const float*)d_in[15];

    int N = in_sizes[1];
    int E = in_sizes[3] / 2;
    int L = in_sizes[4];
    float* out = (float*)d_out;

    float* p_t;
    __half *p_hh, *p_hl, *p_mh, *p_ml, *p_xh, *p_xl;
    __half *w0h, *w0l, *w1h, *w1l, *w2h, *w2l, *wm0h, *wm0l, *wm1h, *wm1l;
    cudaGetSymbolAddress((void**)&p_t,  g_t);
    cudaGetSymbolAddress((void**)&p_hh, g_h_hi);
    cudaGetSymbolAddress((void**)&p_hl, g_h_lo);
    cudaGetSymbolAddress((void**)&p_mh, g_m_hi);
    cudaGetSymbolAddress((void**)&p_ml, g_m_lo);
    cudaGetSymbolAddress((void**)&p_xh, g_x_hi);
    cudaGetSymbolAddress((void**)&p_xl, g_x_lo);
    cudaGetSymbolAddress((void**)&w0h,  g_w0t_hi);  cudaGetSymbolAddress((void**)&w0l,  g_w0t_lo);
    cudaGetSymbolAddress((void**)&w1h,  g_w1t_hi);  cudaGetSymbolAddress((void**)&w1l,  g_w1t_lo);
    cudaGetSymbolAddress((void**)&w2h,  g_w2t_hi);  cudaGetSymbolAddress((void**)&w2l,  g_w2t_lo);
    cudaGetSymbolAddress((void**)&wm0h, g_wm0t_hi); cudaGetSymbolAddress((void**)&wm0l, g_wm0t_lo);
    cudaGetSymbolAddress((void**)&wm1h, g_wm1t_hi); cudaGetSymbolAddress((void**)&wm1l, g_wm1t_lo);

    const int TB = 256;
    const int SMEM128 = 2 * 2 * 128 * 80 + 2 * 2 * 128 * 80;   // 81920
    const int SMEM64  = 2 * 2 * 128 * 80 + 2 * 2 * 64 * 80;    // 61440
    cudaFuncSetAttribute(k_hgemm<128, 0>, cudaFuncAttributeMaxDynamicSharedMemorySize, SMEM128);
    cudaFuncSetAttribute(k_hgemm<128, 1>, cudaFuncAttributeMaxDynamicSharedMemorySize, SMEM128);
    cudaFuncSetAttribute(k_hgemm<64, 2>,  cudaFuncAttributeMaxDynamicSharedMemorySize, SMEM64);

    long long xq = (long long)N * CNFEAT / 4;
    long long nwcell = (long long)N * 32;
    int gy = cdiv(N, 128);

    // launches 1-3: prep needed by GEMM1
    k_split<<<cdiv(xq, TB), TB>>>(x, p_xh, p_xl, xq);
    k_wt<<<cdiv(256 * 512, TB), TB>>>(W0, w0h, w0l, 512, 256);
    k_wt<<<cdiv(256 * 256, TB), TB>>>(W1, w1h, w1l, 256, 256);

    // launch 4 (ncu-captured): GCN layer-1 GEMM
    k_hgemm<128, 0><<<dim3(2, gy), 256, SMEM128>>>(p_xh, p_xl, w0h, w0l,
                                                   p_t, nullptr, nullptr, nullptr,
                                                   N, 256, 512);

    // remaining prep (overlap-ish; all independent of GEMM1 output)
    k_wt<<<cdiv(256 * 256, TB), TB>>>(W2, w2h, w2l, 256, 256);
    k_wt<<<cdiv(512 * 256, TB), TB>>>(Wm0, wm0h, wm0l, 256, 512);
    k_wt<<<cdiv(64 * 512, TB), TB>>>(Wm1, wm1h, wm1l, 512, 64);
    k_lab_init<<<cdiv(N, TB), TB>>>(N);
    k_lab_set<<<cdiv(L, TB), TB>>>(idxl, y, L);
    k_zero_cnt<<<cdiv(N, TB), TB>>>(N);
    k_count<<<cdiv(E, TB), TB>>>(adj, E);
    k_scan<<<1, 1024>>>(N, E);
    k_dinv<<<cdiv(N, TB), TB>>>(N);
    k_fill<<<cdiv(E, TB), TB>>>(adj, E);

    // layer 1 finish
    k_lab_add<<<cdiv(nwcell, TB), TB>>>(W0, N);
    k_agg_csr<<<cdiv(nwcell, TB), TB>>>(p_t, p_hh, p_hl, b0, N);

    // GCN layer 2
    k_hgemm<128, 0><<<dim3(2, gy), 256, SMEM128>>>(p_hh, p_hl, w1h, w1l,
                                                   p_t, nullptr, nullptr, nullptr,
                                                   N, 256, 256);
    k_agg_csr<<<cdiv(nwcell, TB), TB>>>(p_t, p_hh, p_hl, b1, N);

    // GCN layer 3
    k_hgemm<128, 0><<<dim3(2, gy), 256, SMEM128>>>(p_hh, p_hl, w2h, w2l,
                                                   p_t, nullptr, nullptr, nullptr,
                                                   N, 256, 256);
    k_agg_csr<<<cdiv(nwcell, TB), TB>>>(p_t, p_hh, p_hl, b2, N);

    // MLP head
    k_hgemm<128, 1><<<dim3(4, gy), 256, SMEM128>>>(p_hh, p_hl, wm0h, wm0l,
                                                   nullptr, bm0, p_mh, p_ml,
                                                   N, 512, 256);
    k_hgemm<64, 2><<<dim3(1, gy), 256, SMEM64>>>(p_mh, p_ml, wm1h, wm1l,
                                                 out, bm1, nullptr, nullptr,
                                                 N, 64, 512);

    // log_softmax
    k_logsoftmax64<<<cdiv(nwcell, TB), TB>>>(out, N);
}